// round 14
// baseline (speedup 1.0000x reference)
#include <cuda_runtime.h>
#include <cuda_bf16.h>
#include <math.h>

// Problem constants
#define RB   4096   // B*N rows
#define CC   768
#define NTOK 2048
#define HH   12
#define DD   64

// ---------------- scratch (device globals: allocation-free) ----------------
__device__ __nv_bfloat16 d_h1b [RB * CC];
__device__ __nv_bfloat16 d_qkvb[RB * 3 * CC];
__device__ __nv_bfloat16 d_vt  [2 * HH * DD * NTOK];
__device__ __nv_bfloat16 d_oatb[RB * CC];
__device__ float         d_x1  [RB * CC];
__device__ __nv_bfloat16 d_ffnb[RB * 4 * CC];
__device__ float         d_fc2p[2 * RB * CC];        // split-K partials for FC2
__device__ __nv_bfloat16 d_wqkvT[3 * CC * CC];
__device__ __nv_bfloat16 d_wprojT[CC * CC];
__device__ __nv_bfloat16 d_w1T[4 * CC * CC];
__device__ __nv_bfloat16 d_w2T[CC * 4 * CC];

__device__ __forceinline__ unsigned bf2_as_u32(__nv_bfloat162 v) {
    union { __nv_bfloat162 h; unsigned u; } cvt;
    cvt.h = v;
    return cvt.u;
}

// ---------------- batched fp32 -> bf16 transpose of all 4 weights ------------
__global__ void convT4_kernel(const float* __restrict__ s0, __nv_bfloat16* __restrict__ dq,
                              const float* __restrict__ s1, __nv_bfloat16* __restrict__ dp,
                              const float* __restrict__ s2, __nv_bfloat16* __restrict__ d1,
                              const float* __restrict__ s3, __nv_bfloat16* __restrict__ d2) {
    // tile counts: qkv 72x24=1728, proj 24x24=576, w1 96x24=2304, w2 24x96=2304
    int bid = blockIdx.x;
    const float* src; __nv_bfloat16* dst; int R, Cc, local;
    if (bid < 1728)      { src = s0; dst = dq; R = CC;     Cc = 3 * CC; local = bid; }
    else if (bid < 2304) { src = s1; dst = dp; R = CC;     Cc = CC;     local = bid - 1728; }
    else if (bid < 4608) { src = s2; dst = d1; R = CC;     Cc = 4 * CC; local = bid - 2304; }
    else                 { src = s3; dst = d2; R = 4 * CC; Cc = CC;     local = bid - 4608; }
    int ncx = Cc / 32;
    int bx = (local % ncx) * 32, by = (local / ncx) * 32;

    __shared__ float tile[32][33];
    int tx = threadIdx.x, ty = threadIdx.y;
#pragma unroll
    for (int i = 0; i < 4; i++)
        tile[ty + i * 8][tx] = src[(size_t)(by + ty + i * 8) * Cc + bx + tx];
    __syncthreads();
#pragma unroll
    for (int i = 0; i < 4; i++)
        dst[(size_t)(bx + ty + i * 8) * R + by + tx] = __float2bfloat16(tile[tx][ty + i * 8]);
}

// ---------------- V transpose: qkvb V slice -> vt[bh][d][tok] ---------------
__global__ void vtrans_kernel(const __nv_bfloat16* __restrict__ qkvb,
                              __nv_bfloat16* __restrict__ vt) {
    __shared__ __nv_bfloat16 tile[32][33];
    int tok0 = blockIdx.x * 32, d0 = blockIdx.y * 32, bh = blockIdx.z;
    int b = bh / HH, h = bh % HH;
    int tx = threadIdx.x, ty = threadIdx.y;
#pragma unroll
    for (int i = 0; i < 4; i++) {
        int tok = tok0 + ty + i * 8;
        tile[ty + i * 8][tx] =
            qkvb[(size_t)(b * NTOK + tok) * (3 * CC) + 2 * CC + h * DD + d0 + tx];
    }
    __syncthreads();
#pragma unroll
    for (int i = 0; i < 4; i++) {
        int d = d0 + ty + i * 8;
        vt[(size_t)(bh * DD + d) * NTOK + tok0 + tx] = tile[tx][ty + i * 8];
    }
}

// ---------------- LayerNorm: one block per row, bf16 out ----------------
__global__ void ln_kernel(const float* __restrict__ x, const float* __restrict__ g,
                          const float* __restrict__ b, __nv_bfloat16* __restrict__ out) {
    int row = blockIdx.x, t = threadIdx.x;
    const float* xr = x + (size_t)row * CC;
    float v0 = xr[t], v1 = xr[t + 256], v2 = xr[t + 512];
    float s  = v0 + v1 + v2;
    float ss = v0 * v0 + v1 * v1 + v2 * v2;
#pragma unroll
    for (int o = 16; o > 0; o >>= 1) {
        s  += __shfl_xor_sync(0xffffffffu, s,  o);
        ss += __shfl_xor_sync(0xffffffffu, ss, o);
    }
    __shared__ float rs[8], rss[8], sh_mu, sh_rstd;
    int w = t >> 5, lane = t & 31;
    if (!lane) { rs[w] = s; rss[w] = ss; }
    __syncthreads();
    if (t == 0) {
        float S = 0.f, SS = 0.f;
#pragma unroll
        for (int i = 0; i < 8; i++) { S += rs[i]; SS += rss[i]; }
        float mu  = S * (1.0f / CC);
        float var = SS * (1.0f / CC) - mu * mu;
        sh_mu = mu; sh_rstd = rsqrtf(var + 1e-5f);
    }
    __syncthreads();
    float mu = sh_mu, rstd = sh_rstd;
    __nv_bfloat16* orow = out + (size_t)row * CC;
    orow[t]       = __float2bfloat16((v0 - mu) * rstd * g[t]       + b[t]);
    orow[t + 256] = __float2bfloat16((v1 - mu) * rstd * g[t + 256] + b[t + 256]);
    orow[t + 512] = __float2bfloat16((v2 - mu) * rstd * g[t + 512] + b[t + 512]);
}

// ---------------- combine kernel for FC2 split-K -----------------------------
// out = x1 + (p0 + p1 + bias) * ls
__global__ void combine_fc2(const float* __restrict__ p, const float* __restrict__ x1,
                            const float* __restrict__ bias, const float* __restrict__ ls,
                            float* __restrict__ out) {
    int idx = blockIdx.x * 256 + threadIdx.x;          // float4 index
    int col4 = idx % (CC / 4);
    float4 a = ((const float4*)p)[idx];
    float4 b = ((const float4*)p)[idx + RB * CC / 4];
    float4 r = ((const float4*)x1)[idx];
    float4 bs = ((const float4*)bias)[col4];
    float4 l = ((const float4*)ls)[col4];
    float4 o;
    o.x = r.x + (a.x + b.x + bs.x) * l.x;
    o.y = r.y + (a.y + b.y + bs.y) * l.y;
    o.z = r.z + (a.z + b.z + bs.z) * l.z;
    o.w = r.w + (a.w + b.w + bs.w) * l.w;
    ((float4*)out)[idx] = o;
}

// ---------------- primitives ----------------
__device__ __forceinline__ void cpa16_r(unsigned saddr, const void* gmem) {
    asm volatile("cp.async.cg.shared.global [%0], [%1], 16;\n" :: "r"(saddr), "l"(gmem));
}
__device__ __forceinline__ void cp_commit() { asm volatile("cp.async.commit_group;\n"); }
__device__ __forceinline__ void cp_wait1()  { asm volatile("cp.async.wait_group 1;\n"); }
__device__ __forceinline__ void cp_wait0()  { asm volatile("cp.async.wait_group 0;\n"); }

__device__ __forceinline__ unsigned sw128(unsigned off) {
    return off ^ ((off >> 3) & 0x70);
}

__device__ __forceinline__ void ldsm_x4(unsigned& r0, unsigned& r1, unsigned& r2, unsigned& r3,
                                        unsigned addr) {
    asm volatile("ldmatrix.sync.aligned.m8n8.x4.shared.b16 {%0,%1,%2,%3}, [%4];\n"
                 : "=r"(r0), "=r"(r1), "=r"(r2), "=r"(r3) : "r"(addr));
}

__device__ __forceinline__ void mma_bf16(float& c0, float& c1, float& c2, float& c3,
                                         unsigned a0, unsigned a1, unsigned a2, unsigned a3,
                                         unsigned b0, unsigned b1) {
    asm volatile(
        "mma.sync.aligned.m16n8k16.row.col.f32.bf16.bf16.f32 "
        "{%0,%1,%2,%3}, {%4,%5,%6,%7}, {%8,%9}, {%0,%1,%2,%3};\n"
        : "+f"(c0), "+f"(c1), "+f"(c2), "+f"(c3)
        : "r"(a0), "r"(a1), "r"(a2), "r"(a3), "r"(b0), "r"(b1));
}

// ---------------- bf16 GEMM (NT): C = A[M,K] @ Bt[N,K]^T -------------------
// 128x128 CTA tile, BK=64, 3-stage cp.async pipeline, ldmatrix fragments,
// XOR-swizzled smem (128B rows).
// EPI: 0=+bias, 1=gelu(+bias), 2=resid+(+bias)*ls, 4=split-K raw partial (z=k-slice)
#define BM 128
#define BN 128
#define BK 64
#define STAGE_BYTES  (2 * BM * BK * 2)          // A + B per stage = 32KB
#define GEMM_SMEM    (3 * STAGE_BYTES)          // 96KB

template <int EPI, typename OutT>
__global__ __launch_bounds__(256)
void gemm_bf16(const __nv_bfloat16* __restrict__ A, const __nv_bfloat16* __restrict__ Bt,
               const float* __restrict__ bias, OutT* __restrict__ Cm,
               int M, int Nn, int K, int lda,
               const float* __restrict__ resid, const float* __restrict__ ls) {
    extern __shared__ __nv_bfloat16 smem[];
    unsigned smem_u32 = (unsigned)__cvta_generic_to_shared(smem);

    if (EPI == 4) {
        int kz = blockIdx.z;
        A  += (size_t)kz * K;
        Bt += (size_t)kz * K;
        Cm += (size_t)kz * (size_t)M * Nn;
    }

    int t = threadIdx.x;
    int bm = blockIdx.y * BM, bn = blockIdx.x * BN;
    int w = t >> 5, lane = t & 31;
    int g = lane >> 2, t2 = (lane & 3) * 2;
    int wm = (w >> 2) * 64, wn = (w & 3) * 32;

    int l7 = lane & 7, mmat = lane >> 3;
    unsigned a_row_base = (unsigned)(wm + (mmat & 1) * 8 + l7);
    unsigned a_khalf    = (unsigned)((mmat >> 1) * 16);
    unsigned b_row_base = (unsigned)(wn + (mmat >> 1) * 8 + l7);
    unsigned b_khalf    = (unsigned)((mmat & 1) * 16);

    float acc[4][4][4];
#pragma unroll
    for (int mi = 0; mi < 4; mi++)
#pragma unroll
        for (int ni = 0; ni < 4; ni++)
#pragma unroll
            for (int c = 0; c < 4; c++) acc[mi][ni][c] = 0.f;

    int nk = K / BK;

    auto load_tile = [&](int kt, int s) {
        unsigned abase = smem_u32 + (unsigned)(s * STAGE_BYTES);
        unsigned bbase = abase + (unsigned)(BM * BK * 2);
#pragma unroll
        for (int i = 0; i < 4; i++) {
            int idx = t + 256 * i;
            int row = idx >> 3, seg = idx & 7;
            unsigned off = sw128((unsigned)(row * 128 + seg * 16));
            const __nv_bfloat16* ap = A  + (size_t)(bm + row) * lda + kt * BK + seg * 8;
            const __nv_bfloat16* bp = Bt + (size_t)(bn + row) * lda + kt * BK + seg * 8;
            cpa16_r(abase + off, ap);
            cpa16_r(bbase + off, bp);
        }
    };

    load_tile(0, 0); cp_commit();
    load_tile(1, 1); cp_commit();

    for (int kt = 0; kt < nk; kt++) {
        int s = kt % 3;
        if (kt + 1 < nk) cp_wait1(); else cp_wait0();
        __syncthreads();
        if (kt + 2 < nk) {
            load_tile(kt + 2, (kt + 2) % 3);
            cp_commit();
        }

        unsigned abase = smem_u32 + (unsigned)(s * STAGE_BYTES);
        unsigned bbase = abase + (unsigned)(BM * BK * 2);

#pragma unroll
        for (int ks = 0; ks < 4; ks++) {
            unsigned af[4][4], bfr[4][2];
#pragma unroll
            for (int mi = 0; mi < 4; mi++) {
                unsigned off = sw128((a_row_base + mi * 16) * 128 + (unsigned)(ks * 32) + a_khalf);
                ldsm_x4(af[mi][0], af[mi][1], af[mi][2], af[mi][3], abase + off);
            }
#pragma unroll
            for (int p = 0; p < 2; p++) {
                unsigned off = sw128((b_row_base + p * 16) * 128 + (unsigned)(ks * 32) + b_khalf);
                unsigned r0, r1, r2, r3;
                ldsm_x4(r0, r1, r2, r3, bbase + off);
                bfr[2 * p][0] = r0;     bfr[2 * p][1] = r1;
                bfr[2 * p + 1][0] = r2; bfr[2 * p + 1][1] = r3;
            }
#pragma unroll
            for (int mi = 0; mi < 4; mi++)
#pragma unroll
                for (int ni = 0; ni < 4; ni++)
                    mma_bf16(acc[mi][ni][0], acc[mi][ni][1], acc[mi][ni][2], acc[mi][ni][3],
                             af[mi][0], af[mi][1], af[mi][2], af[mi][3],
                             bfr[ni][0], bfr[ni][1]);
        }
        __syncthreads();
    }

    // epilogue
#pragma unroll
    for (int mi = 0; mi < 4; mi++) {
#pragma unroll
        for (int half = 0; half < 2; half++) {
            int m = bm + wm + mi * 16 + g + half * 8;
#pragma unroll
            for (int ni = 0; ni < 4; ni++) {
                int col = bn + wn + ni * 8 + t2;
                float v0 = acc[mi][ni][half * 2 + 0];
                float v1 = acc[mi][ni][half * 2 + 1];
                if (EPI != 4) { v0 += bias[col]; v1 += bias[col + 1]; }
                if (EPI == 1) {
                    v0 = 0.5f * v0 * (1.0f + erff(v0 * 0.70710678118654752f));
                    v1 = 0.5f * v1 * (1.0f + erff(v1 * 0.70710678118654752f));
                } else if (EPI == 2) {
                    const float* rp = resid + (size_t)m * Nn + col;
                    v0 = rp[0] + v0 * ls[col];
                    v1 = rp[1] + v1 * ls[col + 1];
                }
                OutT* cp = Cm + (size_t)m * Nn + col;
                if (sizeof(OutT) == 4) {
                    *(float2*)cp = make_float2(v0, v1);
                } else {
                    *(__nv_bfloat162*)cp = __floats2bfloat162_rn(v0, v1);
                }
            }
        }
    }
}

// ---------------- bf16 tensor-core flash attention (ldmatrix fragments) ------
#define QT 128
#define KT 64
#define AST 72

__global__ __launch_bounds__(256)
void attn_mma_kernel(const __nv_bfloat16* __restrict__ qkvb,
                     const __nv_bfloat16* __restrict__ vt,
                     const unsigned char* __restrict__ mask,
                     __nv_bfloat16* __restrict__ o) {
    __shared__ __nv_bfloat16 Qs[QT][AST];
    __shared__ __nv_bfloat16 Ks[KT][AST];
    __shared__ __nv_bfloat16 Vts[DD][AST];

    int t = threadIdx.x;
    int w = t >> 5, lane = t & 31;
    int g = lane >> 2, t2 = (lane & 3) * 2;
    int qt = blockIdx.x, bh = blockIdx.y;
    int b = bh / HH, head = bh % HH;
    int qbase = qt * QT;
    size_t base = (size_t)b * NTOK;

    unsigned Qu = (unsigned)__cvta_generic_to_shared(&Qs[0][0]);
    unsigned Ku = (unsigned)__cvta_generic_to_shared(&Ks[0][0]);
    unsigned Vu = (unsigned)__cvta_generic_to_shared(&Vts[0][0]);
    int l7 = lane & 7, mmat = lane >> 3;
    unsigned a_base = Qu +
        (unsigned)(((w * 16 + (mmat & 1) * 8 + l7) * AST + (mmat >> 1) * 8) * 2);
    unsigned kv_off = (unsigned)((((mmat >> 1) * 8 + l7) * AST + (mmat & 1) * 8) * 2);

#pragma unroll
    for (int i = 0; i < 4; i++) {
        int id = t + 256 * i;
        int row = id >> 3, seg = id & 7;
        *(float4*)&Qs[row][seg * 8] =
            *(const float4*)(qkvb + (base + qbase + row) * (size_t)(3 * CC) + head * DD + seg * 8);
    }

    int r0 = w * 16 + g;
    const unsigned char* mrow0 = mask + (size_t)(qbase + r0) * NTOK;
    const unsigned char* mrow1 = mrow0 + (size_t)8 * NTOK;

    float m0 = -1e30f, m1 = -1e30f, l0 = 0.f, l1 = 0.f;
    float oacc[8][4];
#pragma unroll
    for (int nd = 0; nd < 8; nd++)
#pragma unroll
        for (int c = 0; c < 4; c++) oacc[nd][c] = 0.f;

    for (int kt2 = 0; kt2 < NTOK / KT; kt2++) {
        int kbase = kt2 * KT;
        __syncthreads();
#pragma unroll
        for (int i = 0; i < 2; i++) {
            int id = t + 256 * i;
            int row = id >> 3, seg = id & 7;
            *(float4*)&Ks[row][seg * 8] =
                *(const float4*)(qkvb + (base + kbase + row) * (size_t)(3 * CC) + CC + head * DD + seg * 8);
            *(float4*)&Vts[row][seg * 8] =
                *(const float4*)(vt + (size_t)(bh * DD + row) * NTOK + kbase + seg * 8);
        }
        __syncthreads();

        float sacc[8][4];
#pragma unroll
        for (int nb = 0; nb < 8; nb++)
#pragma unroll
            for (int c = 0; c < 4; c++) sacc[nb][c] = 0.f;
#pragma unroll
        for (int ds = 0; ds < 4; ds++) {
            unsigned a0, a1, a2, a3;
            ldsm_x4(a0, a1, a2, a3, a_base + (unsigned)(ds * 32));
#pragma unroll
            for (int p = 0; p < 4; p++) {
                unsigned r0v, r1v, r2v, r3v;
                ldsm_x4(r0v, r1v, r2v, r3v,
                        Ku + (unsigned)(p * 16 * AST * 2) + kv_off + (unsigned)(ds * 32));
                mma_bf16(sacc[2 * p][0], sacc[2 * p][1], sacc[2 * p][2], sacc[2 * p][3],
                         a0, a1, a2, a3, r0v, r1v);
                mma_bf16(sacc[2 * p + 1][0], sacc[2 * p + 1][1],
                         sacc[2 * p + 1][2], sacc[2 * p + 1][3],
                         a0, a1, a2, a3, r2v, r3v);
            }
        }

        float rmax0 = -1e30f, rmax1 = -1e30f;
#pragma unroll
        for (int nb = 0; nb < 8; nb++) {
            uchar2 mq0 = *(const uchar2*)(mrow0 + kbase + nb * 8 + t2);
            uchar2 mq1 = *(const uchar2*)(mrow1 + kbase + nb * 8 + t2);
            float s00 = mq0.x ? -1e30f : sacc[nb][0] * 0.125f;
            float s01 = mq0.y ? -1e30f : sacc[nb][1] * 0.125f;
            float s10 = mq1.x ? -1e30f : sacc[nb][2] * 0.125f;
            float s11 = mq1.y ? -1e30f : sacc[nb][3] * 0.125f;
            sacc[nb][0] = s00; sacc[nb][1] = s01; sacc[nb][2] = s10; sacc[nb][3] = s11;
            rmax0 = fmaxf(rmax0, fmaxf(s00, s01));
            rmax1 = fmaxf(rmax1, fmaxf(s10, s11));
        }
#pragma unroll
        for (int off = 1; off < 4; off <<= 1) {
            rmax0 = fmaxf(rmax0, __shfl_xor_sync(0xffffffffu, rmax0, off));
            rmax1 = fmaxf(rmax1, __shfl_xor_sync(0xffffffffu, rmax1, off));
        }
        float mn0 = fmaxf(m0, rmax0), mn1 = fmaxf(m1, rmax1);
        float al0 = __expf(m0 - mn0), al1 = __expf(m1 - mn1);
        m0 = mn0; m1 = mn1;

        unsigned pr0[8], pr1[8];
        float rs0 = 0.f, rs1 = 0.f;
#pragma unroll
        for (int nb = 0; nb < 8; nb++) {
            float p00 = __expf(sacc[nb][0] - mn0);
            float p01 = __expf(sacc[nb][1] - mn0);
            float p10 = __expf(sacc[nb][2] - mn1);
            float p11 = __expf(sacc[nb][3] - mn1);
            rs0 += p00 + p01; rs1 += p10 + p11;
            pr0[nb] = bf2_as_u32(__floats2bfloat162_rn(p00, p01));
            pr1[nb] = bf2_as_u32(__floats2bfloat162_rn(p10, p11));
        }
#pragma unroll
        for (int off = 1; off < 4; off <<= 1) {
            rs0 += __shfl_xor_sync(0xffffffffu, rs0, off);
            rs1 += __shfl_xor_sync(0xffffffffu, rs1, off);
        }
        l0 = l0 * al0 + rs0;
        l1 = l1 * al1 + rs1;

#pragma unroll
        for (int nd = 0; nd < 8; nd++) {
            oacc[nd][0] *= al0; oacc[nd][1] *= al0;
            oacc[nd][2] *= al1; oacc[nd][3] *= al1;
        }
#pragma unroll
        for (int kb = 0; kb < 4; kb++) {
            unsigned a0 = pr0[2 * kb],     a1 = pr1[2 * kb];
            unsigned a2 = pr0[2 * kb + 1], a3 = pr1[2 * kb + 1];
#pragma unroll
            for (int p = 0; p < 4; p++) {
                unsigned r0v, r1v, r2v, r3v;
                ldsm_x4(r0v, r1v, r2v, r3v,
                        Vu + (unsigned)(p * 16 * AST * 2) + kv_off + (unsigned)(kb * 32));
                mma_bf16(oacc[2 * p][0], oacc[2 * p][1], oacc[2 * p][2], oacc[2 * p][3],
                         a0, a1, a2, a3, r0v, r1v);
                mma_bf16(oacc[2 * p + 1][0], oacc[2 * p + 1][1],
                         oacc[2 * p + 1][2], oacc[2 * p + 1][3],
                         a0, a1, a2, a3, r2v, r3v);
            }
        }
    }

    float inv0 = 1.0f / l0, inv1 = 1.0f / l1;
    __nv_bfloat16* op0 = o + (base + qbase + r0) * (size_t)CC + head * DD;
    __nv_bfloat16* op1 = op0 + (size_t)8 * CC;
#pragma unroll
    for (int nd = 0; nd < 8; nd++) {
        *(__nv_bfloat162*)(op0 + nd * 8 + t2) =
            __floats2bfloat162_rn(oacc[nd][0] * inv0, oacc[nd][1] * inv0);
        *(__nv_bfloat162*)(op1 + nd * 8 + t2) =
            __floats2bfloat162_rn(oacc[nd][2] * inv1, oacc[nd][3] * inv1);
    }
}

// ---------------- launch ----------------
extern "C" void kernel_launch(void* const* d_in, const int* in_sizes, int n_in,
                              void* d_out, int out_size) {
    (void)in_sizes; (void)n_in; (void)out_size;
    const float* x            = (const float*)d_in[0];
    const unsigned char* mask = (const unsigned char*)d_in[1];
    const float* ln1_g  = (const float*)d_in[2];
    const float* ln1_b  = (const float*)d_in[3];
    const float* w_qkv  = (const float*)d_in[4];
    const float* b_qkv  = (const float*)d_in[5];
    const float* w_proj = (const float*)d_in[6];
    const float* b_proj = (const float*)d_in[7];
    const float* ls1    = (const float*)d_in[8];
    const float* ln2_g  = (const float*)d_in[9];
    const float* ln2_b  = (const float*)d_in[10];
    const float* w1     = (const float*)d_in[11];
    const float* b1     = (const float*)d_in[12];
    const float* w2     = (const float*)d_in[13];
    const float* b2     = (const float*)d_in[14];
    const float* ls2    = (const float*)d_in[15];
    float* out = (float*)d_out;

    __nv_bfloat16 *h1b, *qkvb, *vt, *oatb, *ffnb, *wqkvT, *wprojT, *w1T, *w2T;
    float *x1, *fc2p;
    cudaGetSymbolAddress((void**)&h1b,   d_h1b);
    cudaGetSymbolAddress((void**)&qkvb,  d_qkvb);
    cudaGetSymbolAddress((void**)&vt,    d_vt);
    cudaGetSymbolAddress((void**)&oatb,  d_oatb);
    cudaGetSymbolAddress((void**)&x1,    d_x1);
    cudaGetSymbolAddress((void**)&ffnb,  d_ffnb);
    cudaGetSymbolAddress((void**)&fc2p,  d_fc2p);
    cudaGetSymbolAddress((void**)&wqkvT, d_wqkvT);
    cudaGetSymbolAddress((void**)&wprojT,d_wprojT);
    cudaGetSymbolAddress((void**)&w1T,   d_w1T);
    cudaGetSymbolAddress((void**)&w2T,   d_w2T);

    cudaFuncSetAttribute(gemm_bf16<0, __nv_bfloat16>,
                         cudaFuncAttributeMaxDynamicSharedMemorySize, GEMM_SMEM);
    cudaFuncSetAttribute(gemm_bf16<1, __nv_bfloat16>,
                         cudaFuncAttributeMaxDynamicSharedMemorySize, GEMM_SMEM);
    cudaFuncSetAttribute(gemm_bf16<2, float>,
                         cudaFuncAttributeMaxDynamicSharedMemorySize, GEMM_SMEM);
    cudaFuncSetAttribute(gemm_bf16<4, float>,
                         cudaFuncAttributeMaxDynamicSharedMemorySize, GEMM_SMEM);

    dim3 tb(32, 8);
    convT4_kernel<<<6912, tb>>>(w_qkv, wqkvT, w_proj, wprojT, w1, w1T, w2, w2T);   // 0
    ln_kernel<<<RB, 256>>>(x, ln1_g, ln1_b, h1b);                                   // 1
    gemm_bf16<0, __nv_bfloat16><<<dim3(3 * CC / BN, RB / BM), 256, GEMM_SMEM>>>(    // 2
        h1b, wqkvT, b_qkv, qkvb, RB, 3 * CC, CC, CC, nullptr, nullptr);
    vtrans_kernel<<<dim3(NTOK / 32, DD / 32, 2 * HH), tb>>>(qkvb, vt);              // 3
    attn_mma_kernel<<<dim3(NTOK / QT, 2 * HH), 256>>>(qkvb, vt, mask, oatb);        // 4
    gemm_bf16<2, float><<<dim3(CC / BN, RB / BM), 256, GEMM_SMEM>>>(                // 5
        oatb, wprojT, b_proj, x1, RB, CC, CC, CC, x, ls1);
    ln_kernel<<<RB, 256>>>(x1, ln2_g, ln2_b, h1b);                                  // 6
    gemm_bf16<1, __nv_bfloat16><<<dim3(4 * CC / BN, RB / BM), 256, GEMM_SMEM>>>(    // 7
        h1b, w1T, b1, ffnb, RB, 4 * CC, CC, CC, nullptr, nullptr);
    // FC2 split-K=2: partials then combine
    gemm_bf16<4, float><<<dim3(CC / BN, RB / BM, 2), 256, GEMM_SMEM>>>(             // 8
        ffnb, w2T, b2, fc2p, RB, CC, 2 * CC, 4 * CC, nullptr, nullptr);
    combine_fc2<<<RB * CC / 4 / 256, 256>>>(fc2p, x1, b2, ls2, out);                // 9
}

// round 15
// speedup vs baseline: 1.0687x; 1.0687x over previous
#include <cuda_runtime.h>
#include <cuda_bf16.h>
#include <math.h>

// Problem constants
#define RB   4096   // B*N rows
#define CC   768
#define NTOK 2048
#define HH   12
#define DD   64

// ---------------- scratch (device globals: allocation-free) ----------------
__device__ __nv_bfloat16 d_h1b [RB * CC];
__device__ __nv_bfloat16 d_qkvb[RB * 3 * CC];
__device__ __nv_bfloat16 d_vt  [2 * HH * DD * NTOK];
__device__ __nv_bfloat16 d_oatb[RB * CC];
__device__ float         d_x1  [RB * CC];
__device__ __nv_bfloat16 d_ffnb[RB * 4 * CC];
__device__ __nv_bfloat16 d_wqkvT[3 * CC * CC];
__device__ __nv_bfloat16 d_wprojT[CC * CC];
__device__ __nv_bfloat16 d_w1T[4 * CC * CC];
__device__ __nv_bfloat16 d_w2T[CC * 4 * CC];

__device__ __forceinline__ unsigned bf2_as_u32(__nv_bfloat162 v) {
    union { __nv_bfloat162 h; unsigned u; } cvt;
    cvt.h = v;
    return cvt.u;
}

// ---------------- batched fp32 -> bf16 transpose of all 4 weights ------------
__global__ void convT4_kernel(const float* __restrict__ s0, __nv_bfloat16* __restrict__ dq,
                              const float* __restrict__ s1, __nv_bfloat16* __restrict__ dp,
                              const float* __restrict__ s2, __nv_bfloat16* __restrict__ d1,
                              const float* __restrict__ s3, __nv_bfloat16* __restrict__ d2) {
    // tile counts: qkv 72x24=1728, proj 24x24=576, w1 96x24=2304, w2 24x96=2304
    int bid = blockIdx.x;
    const float* src; __nv_bfloat16* dst; int R, Cc, local;
    if (bid < 1728)      { src = s0; dst = dq; R = CC;     Cc = 3 * CC; local = bid; }
    else if (bid < 2304) { src = s1; dst = dp; R = CC;     Cc = CC;     local = bid - 1728; }
    else if (bid < 4608) { src = s2; dst = d1; R = CC;     Cc = 4 * CC; local = bid - 2304; }
    else                 { src = s3; dst = d2; R = 4 * CC; Cc = CC;     local = bid - 4608; }
    int ncx = Cc / 32;
    int bx = (local % ncx) * 32, by = (local / ncx) * 32;

    __shared__ float tile[32][33];
    int tx = threadIdx.x, ty = threadIdx.y;
#pragma unroll
    for (int i = 0; i < 4; i++)
        tile[ty + i * 8][tx] = src[(size_t)(by + ty + i * 8) * Cc + bx + tx];
    __syncthreads();
#pragma unroll
    for (int i = 0; i < 4; i++)
        dst[(size_t)(bx + ty + i * 8) * R + by + tx] = __float2bfloat16(tile[tx][ty + i * 8]);
}

// ---------------- V transpose: qkvb V slice -> vt[bh][d][tok] ---------------
__global__ void vtrans_kernel(const __nv_bfloat16* __restrict__ qkvb,
                              __nv_bfloat16* __restrict__ vt) {
    __shared__ __nv_bfloat16 tile[32][33];
    int tok0 = blockIdx.x * 32, d0 = blockIdx.y * 32, bh = blockIdx.z;
    int b = bh / HH, h = bh % HH;
    int tx = threadIdx.x, ty = threadIdx.y;
#pragma unroll
    for (int i = 0; i < 4; i++) {
        int tok = tok0 + ty + i * 8;
        tile[ty + i * 8][tx] =
            qkvb[(size_t)(b * NTOK + tok) * (3 * CC) + 2 * CC + h * DD + d0 + tx];
    }
    __syncthreads();
#pragma unroll
    for (int i = 0; i < 4; i++) {
        int d = d0 + ty + i * 8;
        vt[(size_t)(bh * DD + d) * NTOK + tok0 + tx] = tile[tx][ty + i * 8];
    }
}

// ---------------- LayerNorm: one block per row, bf16 out ----------------
__global__ void ln_kernel(const float* __restrict__ x, const float* __restrict__ g,
                          const float* __restrict__ b, __nv_bfloat16* __restrict__ out) {
    int row = blockIdx.x, t = threadIdx.x;
    const float* xr = x + (size_t)row * CC;
    float v0 = xr[t], v1 = xr[t + 256], v2 = xr[t + 512];
    float s  = v0 + v1 + v2;
    float ss = v0 * v0 + v1 * v1 + v2 * v2;
#pragma unroll
    for (int o = 16; o > 0; o >>= 1) {
        s  += __shfl_xor_sync(0xffffffffu, s,  o);
        ss += __shfl_xor_sync(0xffffffffu, ss, o);
    }
    __shared__ float rs[8], rss[8], sh_mu, sh_rstd;
    int w = t >> 5, lane = t & 31;
    if (!lane) { rs[w] = s; rss[w] = ss; }
    __syncthreads();
    if (t == 0) {
        float S = 0.f, SS = 0.f;
#pragma unroll
        for (int i = 0; i < 8; i++) { S += rs[i]; SS += rss[i]; }
        float mu  = S * (1.0f / CC);
        float var = SS * (1.0f / CC) - mu * mu;
        sh_mu = mu; sh_rstd = rsqrtf(var + 1e-5f);
    }
    __syncthreads();
    float mu = sh_mu, rstd = sh_rstd;
    __nv_bfloat16* orow = out + (size_t)row * CC;
    orow[t]       = __float2bfloat16((v0 - mu) * rstd * g[t]       + b[t]);
    orow[t + 256] = __float2bfloat16((v1 - mu) * rstd * g[t + 256] + b[t + 256]);
    orow[t + 512] = __float2bfloat16((v2 - mu) * rstd * g[t + 512] + b[t + 512]);
}

// ---------------- primitives ----------------
__device__ __forceinline__ void cpa16_r(unsigned saddr, const void* gmem) {
    asm volatile("cp.async.cg.shared.global [%0], [%1], 16;\n" :: "r"(saddr), "l"(gmem));
}
__device__ __forceinline__ void cp_commit() { asm volatile("cp.async.commit_group;\n"); }
__device__ __forceinline__ void cp_wait1()  { asm volatile("cp.async.wait_group 1;\n"); }
__device__ __forceinline__ void cp_wait0()  { asm volatile("cp.async.wait_group 0;\n"); }

__device__ __forceinline__ unsigned sw128(unsigned off) {
    return off ^ ((off >> 3) & 0x70);
}

__device__ __forceinline__ void ldsm_x4(unsigned& r0, unsigned& r1, unsigned& r2, unsigned& r3,
                                        unsigned addr) {
    asm volatile("ldmatrix.sync.aligned.m8n8.x4.shared.b16 {%0,%1,%2,%3}, [%4];\n"
                 : "=r"(r0), "=r"(r1), "=r"(r2), "=r"(r3) : "r"(addr));
}

__device__ __forceinline__ void mma_bf16(float& c0, float& c1, float& c2, float& c3,
                                         unsigned a0, unsigned a1, unsigned a2, unsigned a3,
                                         unsigned b0, unsigned b1) {
    asm volatile(
        "mma.sync.aligned.m16n8k16.row.col.f32.bf16.bf16.f32 "
        "{%0,%1,%2,%3}, {%4,%5,%6,%7}, {%8,%9}, {%0,%1,%2,%3};\n"
        : "+f"(c0), "+f"(c1), "+f"(c2), "+f"(c3)
        : "r"(a0), "r"(a1), "r"(a2), "r"(a3), "r"(b0), "r"(b1));
}

// ---------------- bf16 GEMM (NT): C = A[M,K] @ Bt[N,K]^T -------------------
// 128x128 CTA tile, BK=64, 3-stage cp.async pipeline, ldmatrix fragments,
// XOR-swizzled smem (128B rows).   [identical to the proven R13 version]
#define BM 128
#define BN 128
#define BK 64
#define STAGE_BYTES  (2 * BM * BK * 2)          // A + B per stage = 32KB
#define GEMM_SMEM    (3 * STAGE_BYTES)          // 96KB

template <int EPI, typename OutT>
__global__ __launch_bounds__(256)
void gemm_bf16(const __nv_bfloat16* __restrict__ A, const __nv_bfloat16* __restrict__ Bt,
               const float* __restrict__ bias, OutT* __restrict__ Cm,
               int M, int Nn, int K,
               const float* __restrict__ resid, const float* __restrict__ ls) {
    extern __shared__ __nv_bfloat16 smem[];
    unsigned smem_u32 = (unsigned)__cvta_generic_to_shared(smem);

    int t = threadIdx.x;
    int bm = blockIdx.y * BM, bn = blockIdx.x * BN;
    int w = t >> 5, lane = t & 31;
    int g = lane >> 2, t2 = (lane & 3) * 2;
    int wm = (w >> 2) * 64, wn = (w & 3) * 32;

    int l7 = lane & 7, mmat = lane >> 3;
    unsigned a_row_base = (unsigned)(wm + (mmat & 1) * 8 + l7);
    unsigned a_khalf    = (unsigned)((mmat >> 1) * 16);
    unsigned b_row_base = (unsigned)(wn + (mmat >> 1) * 8 + l7);
    unsigned b_khalf    = (unsigned)((mmat & 1) * 16);

    float acc[4][4][4];
#pragma unroll
    for (int mi = 0; mi < 4; mi++)
#pragma unroll
        for (int ni = 0; ni < 4; ni++)
#pragma unroll
            for (int c = 0; c < 4; c++) acc[mi][ni][c] = 0.f;

    int nk = K / BK;

    auto load_tile = [&](int kt, int s) {
        unsigned abase = smem_u32 + (unsigned)(s * STAGE_BYTES);
        unsigned bbase = abase + (unsigned)(BM * BK * 2);
#pragma unroll
        for (int i = 0; i < 4; i++) {
            int idx = t + 256 * i;
            int row = idx >> 3, seg = idx & 7;
            unsigned off = sw128((unsigned)(row * 128 + seg * 16));
            const __nv_bfloat16* ap = A  + (size_t)(bm + row) * K + kt * BK + seg * 8;
            const __nv_bfloat16* bp = Bt + (size_t)(bn + row) * K + kt * BK + seg * 8;
            cpa16_r(abase + off, ap);
            cpa16_r(bbase + off, bp);
        }
    };

    load_tile(0, 0); cp_commit();
    load_tile(1, 1); cp_commit();

    for (int kt = 0; kt < nk; kt++) {
        int s = kt % 3;
        if (kt + 1 < nk) cp_wait1(); else cp_wait0();
        __syncthreads();
        if (kt + 2 < nk) {
            load_tile(kt + 2, (kt + 2) % 3);
            cp_commit();
        }

        unsigned abase = smem_u32 + (unsigned)(s * STAGE_BYTES);
        unsigned bbase = abase + (unsigned)(BM * BK * 2);

#pragma unroll
        for (int ks = 0; ks < 4; ks++) {
            unsigned af[4][4], bfr[4][2];
#pragma unroll
            for (int mi = 0; mi < 4; mi++) {
                unsigned off = sw128((a_row_base + mi * 16) * 128 + (unsigned)(ks * 32) + a_khalf);
                ldsm_x4(af[mi][0], af[mi][1], af[mi][2], af[mi][3], abase + off);
            }
#pragma unroll
            for (int p = 0; p < 2; p++) {
                unsigned off = sw128((b_row_base + p * 16) * 128 + (unsigned)(ks * 32) + b_khalf);
                unsigned r0, r1, r2, r3;
                ldsm_x4(r0, r1, r2, r3, bbase + off);
                bfr[2 * p][0] = r0;     bfr[2 * p][1] = r1;
                bfr[2 * p + 1][0] = r2; bfr[2 * p + 1][1] = r3;
            }
#pragma unroll
            for (int mi = 0; mi < 4; mi++)
#pragma unroll
                for (int ni = 0; ni < 4; ni++)
                    mma_bf16(acc[mi][ni][0], acc[mi][ni][1], acc[mi][ni][2], acc[mi][ni][3],
                             af[mi][0], af[mi][1], af[mi][2], af[mi][3],
                             bfr[ni][0], bfr[ni][1]);
        }
        __syncthreads();
    }

    // epilogue
#pragma unroll
    for (int mi = 0; mi < 4; mi++) {
#pragma unroll
        for (int half = 0; half < 2; half++) {
            int m = bm + wm + mi * 16 + g + half * 8;
#pragma unroll
            for (int ni = 0; ni < 4; ni++) {
                int col = bn + wn + ni * 8 + t2;
                float v0 = acc[mi][ni][half * 2 + 0] + bias[col];
                float v1 = acc[mi][ni][half * 2 + 1] + bias[col + 1];
                if (EPI == 1) {
                    v0 = 0.5f * v0 * (1.0f + erff(v0 * 0.70710678118654752f));
                    v1 = 0.5f * v1 * (1.0f + erff(v1 * 0.70710678118654752f));
                } else if (EPI == 2) {
                    const float* rp = resid + (size_t)m * Nn + col;
                    v0 = rp[0] + v0 * ls[col];
                    v1 = rp[1] + v1 * ls[col + 1];
                }
                OutT* cp = Cm + (size_t)m * Nn + col;
                if (sizeof(OutT) == 4) {
                    *(float2*)cp = make_float2(v0, v1);
                } else {
                    *(__nv_bfloat162*)cp = __floats2bfloat162_rn(v0, v1);
                }
            }
        }
    }
}

// ---------------- bf16 flash attention: cp.async K/V + ldmatrix fragments ----
// 128 q-rows/block, 64-key tiles, 8 warps x 16 q-rows, double-buffered K/V.
#define QT 128
#define KT 64
#define AST 72
#define ATTN_SMEM ((QT + 4 * KT) * AST * 2)    // Q + 2xK + 2xV = 55296 B

__global__ __launch_bounds__(256)
void attn_mma_kernel(const __nv_bfloat16* __restrict__ qkvb,
                     const __nv_bfloat16* __restrict__ vt,
                     const unsigned char* __restrict__ mask,
                     __nv_bfloat16* __restrict__ o) {
    extern __shared__ __nv_bfloat16 ash[];
    unsigned Qu = (unsigned)__cvta_generic_to_shared(ash);
    unsigned Ku = Qu + QT * AST * 2;
    unsigned Vu = Ku + 2 * KT * AST * 2;

    int t = threadIdx.x;
    int w = t >> 5, lane = t & 31;
    int g = lane >> 2, t2 = (lane & 3) * 2;
    int qt = blockIdx.x, bh = blockIdx.y;
    int b = bh / HH, head = bh % HH;
    int qbase = qt * QT;
    size_t base = (size_t)b * NTOK;

    int l7 = lane & 7, mmat = lane >> 3;
    unsigned a_base = Qu +
        (unsigned)(((w * 16 + (mmat & 1) * 8 + l7) * AST + (mmat >> 1) * 8) * 2);
    unsigned kv_off = (unsigned)((((mmat >> 1) * 8 + l7) * AST + (mmat & 1) * 8) * 2);

    auto load_kv = [&](int kt2, int buf) {
        int kbase = kt2 * KT;
        unsigned kb = Ku + (unsigned)(buf * KT * AST * 2);
        unsigned vb = Vu + (unsigned)(buf * KT * AST * 2);
#pragma unroll
        for (int i = 0; i < 2; i++) {
            int id = t + 256 * i;
            int row = id >> 3, seg = id & 7;
            cpa16_r(kb + (unsigned)(row * AST * 2 + seg * 16),
                    qkvb + (base + kbase + row) * (size_t)(3 * CC) + CC + head * DD + seg * 8);
            cpa16_r(vb + (unsigned)(row * AST * 2 + seg * 16),
                    vt + (size_t)(bh * DD + row) * NTOK + kbase + seg * 8);
        }
        cp_commit();
    };

    // Q + tile 0 share commit group 0
#pragma unroll
    for (int i = 0; i < 4; i++) {
        int id = t + 256 * i;
        int row = id >> 3, seg = id & 7;
        cpa16_r(Qu + (unsigned)(row * AST * 2 + seg * 16),
                qkvb + (base + qbase + row) * (size_t)(3 * CC) + head * DD + seg * 8);
    }
    load_kv(0, 0);

    int r0 = w * 16 + g;
    const unsigned char* mrow0 = mask + (size_t)(qbase + r0) * NTOK;
    const unsigned char* mrow1 = mrow0 + (size_t)8 * NTOK;

    float m0 = -1e30f, m1 = -1e30f, l0 = 0.f, l1 = 0.f;
    float oacc[8][4];
#pragma unroll
    for (int nd = 0; nd < 8; nd++)
#pragma unroll
        for (int c = 0; c < 4; c++) oacc[nd][c] = 0.f;

    for (int kt2 = 0; kt2 < NTOK / KT; kt2++) {
        int buf = kt2 & 1;
        int kbase = kt2 * KT;
        cp_wait0();
        __syncthreads();
        if (kt2 + 1 < NTOK / KT) load_kv(kt2 + 1, buf ^ 1);

        unsigned Kbuf = Ku + (unsigned)(buf * KT * AST * 2);
        unsigned Vbuf = Vu + (unsigned)(buf * KT * AST * 2);

        // S = Q @ K^T
        float sacc[8][4];
#pragma unroll
        for (int nb = 0; nb < 8; nb++)
#pragma unroll
            for (int c = 0; c < 4; c++) sacc[nb][c] = 0.f;
#pragma unroll
        for (int ds = 0; ds < 4; ds++) {
            unsigned a0, a1, a2, a3;
            ldsm_x4(a0, a1, a2, a3, a_base + (unsigned)(ds * 32));
#pragma unroll
            for (int p = 0; p < 4; p++) {
                unsigned r0v, r1v, r2v, r3v;
                ldsm_x4(r0v, r1v, r2v, r3v,
                        Kbuf + (unsigned)(p * 16 * AST * 2) + kv_off + (unsigned)(ds * 32));
                mma_bf16(sacc[2 * p][0], sacc[2 * p][1], sacc[2 * p][2], sacc[2 * p][3],
                         a0, a1, a2, a3, r0v, r1v);
                mma_bf16(sacc[2 * p + 1][0], sacc[2 * p + 1][1],
                         sacc[2 * p + 1][2], sacc[2 * p + 1][3],
                         a0, a1, a2, a3, r2v, r3v);
            }
        }

        // scale + mask + row max
        float rmax0 = -1e30f, rmax1 = -1e30f;
#pragma unroll
        for (int nb = 0; nb < 8; nb++) {
            uchar2 mq0 = *(const uchar2*)(mrow0 + kbase + nb * 8 + t2);
            uchar2 mq1 = *(const uchar2*)(mrow1 + kbase + nb * 8 + t2);
            float s00 = mq0.x ? -1e30f : sacc[nb][0] * 0.125f;
            float s01 = mq0.y ? -1e30f : sacc[nb][1] * 0.125f;
            float s10 = mq1.x ? -1e30f : sacc[nb][2] * 0.125f;
            float s11 = mq1.y ? -1e30f : sacc[nb][3] * 0.125f;
            sacc[nb][0] = s00; sacc[nb][1] = s01; sacc[nb][2] = s10; sacc[nb][3] = s11;
            rmax0 = fmaxf(rmax0, fmaxf(s00, s01));
            rmax1 = fmaxf(rmax1, fmaxf(s10, s11));
        }
#pragma unroll
        for (int off = 1; off < 4; off <<= 1) {
            rmax0 = fmaxf(rmax0, __shfl_xor_sync(0xffffffffu, rmax0, off));
            rmax1 = fmaxf(rmax1, __shfl_xor_sync(0xffffffffu, rmax1, off));
        }
        float mn0 = fmaxf(m0, rmax0), mn1 = fmaxf(m1, rmax1);
        float al0 = __expf(m0 - mn0), al1 = __expf(m1 - mn1);
        m0 = mn0; m1 = mn1;

        // exp -> P fragments + row sums
        unsigned pr0[8], pr1[8];
        float rs0 = 0.f, rs1 = 0.f;
#pragma unroll
        for (int nb = 0; nb < 8; nb++) {
            float p00 = __expf(sacc[nb][0] - mn0);
            float p01 = __expf(sacc[nb][1] - mn0);
            float p10 = __expf(sacc[nb][2] - mn1);
            float p11 = __expf(sacc[nb][3] - mn1);
            rs0 += p00 + p01; rs1 += p10 + p11;
            pr0[nb] = bf2_as_u32(__floats2bfloat162_rn(p00, p01));
            pr1[nb] = bf2_as_u32(__floats2bfloat162_rn(p10, p11));
        }
#pragma unroll
        for (int off = 1; off < 4; off <<= 1) {
            rs0 += __shfl_xor_sync(0xffffffffu, rs0, off);
            rs1 += __shfl_xor_sync(0xffffffffu, rs1, off);
        }
        l0 = l0 * al0 + rs0;
        l1 = l1 * al1 + rs1;

        // O = O*alpha + P @ V
#pragma unroll
        for (int nd = 0; nd < 8; nd++) {
            oacc[nd][0] *= al0; oacc[nd][1] *= al0;
            oacc[nd][2] *= al1; oacc[nd][3] *= al1;
        }
#pragma unroll
        for (int kb = 0; kb < 4; kb++) {
            unsigned a0 = pr0[2 * kb],     a1 = pr1[2 * kb];
            unsigned a2 = pr0[2 * kb + 1], a3 = pr1[2 * kb + 1];
#pragma unroll
            for (int p = 0; p < 4; p++) {
                unsigned r0v, r1v, r2v, r3v;
                ldsm_x4(r0v, r1v, r2v, r3v,
                        Vbuf + (unsigned)(p * 16 * AST * 2) + kv_off + (unsigned)(kb * 32));
                mma_bf16(oacc[2 * p][0], oacc[2 * p][1], oacc[2 * p][2], oacc[2 * p][3],
                         a0, a1, a2, a3, r0v, r1v);
                mma_bf16(oacc[2 * p + 1][0], oacc[2 * p + 1][1],
                         oacc[2 * p + 1][2], oacc[2 * p + 1][3],
                         a0, a1, a2, a3, r2v, r3v);
            }
        }
    }

    float inv0 = 1.0f / l0, inv1 = 1.0f / l1;
    __nv_bfloat16* op0 = o + (base + qbase + r0) * (size_t)CC + head * DD;
    __nv_bfloat16* op1 = op0 + (size_t)8 * CC;
#pragma unroll
    for (int nd = 0; nd < 8; nd++) {
        *(__nv_bfloat162*)(op0 + nd * 8 + t2) =
            __floats2bfloat162_rn(oacc[nd][0] * inv0, oacc[nd][1] * inv0);
        *(__nv_bfloat162*)(op1 + nd * 8 + t2) =
            __floats2bfloat162_rn(oacc[nd][2] * inv1, oacc[nd][3] * inv1);
    }
}

// ---------------- launch ----------------
extern "C" void kernel_launch(void* const* d_in, const int* in_sizes, int n_in,
                              void* d_out, int out_size) {
    (void)in_sizes; (void)n_in; (void)out_size;
    const float* x            = (const float*)d_in[0];
    const unsigned char* mask = (const unsigned char*)d_in[1];
    const float* ln1_g  = (const float*)d_in[2];
    const float* ln1_b  = (const float*)d_in[3];
    const float* w_qkv  = (const float*)d_in[4];
    const float* b_qkv  = (const float*)d_in[5];
    const float* w_proj = (const float*)d_in[6];
    const float* b_proj = (const float*)d_in[7];
    const float* ls1    = (const float*)d_in[8];
    const float* ln2_g  = (const float*)d_in[9];
    const float* ln2_b  = (const float*)d_in[10];
    const float* w1     = (const float*)d_in[11];
    const float* b1     = (const float*)d_in[12];
    const float* w2     = (const float*)d_in[13];
    const float* b2     = (const float*)d_in[14];
    const float* ls2    = (const float*)d_in[15];
    float* out = (float*)d_out;

    __nv_bfloat16 *h1b, *qkvb, *vt, *oatb, *ffnb, *wqkvT, *wprojT, *w1T, *w2T;
    float *x1;
    cudaGetSymbolAddress((void**)&h1b,   d_h1b);
    cudaGetSymbolAddress((void**)&qkvb,  d_qkvb);
    cudaGetSymbolAddress((void**)&vt,    d_vt);
    cudaGetSymbolAddress((void**)&oatb,  d_oatb);
    cudaGetSymbolAddress((void**)&x1,    d_x1);
    cudaGetSymbolAddress((void**)&ffnb,  d_ffnb);
    cudaGetSymbolAddress((void**)&wqkvT, d_wqkvT);
    cudaGetSymbolAddress((void**)&wprojT,d_wprojT);
    cudaGetSymbolAddress((void**)&w1T,   d_w1T);
    cudaGetSymbolAddress((void**)&w2T,   d_w2T);

    cudaFuncSetAttribute(gemm_bf16<0, __nv_bfloat16>,
                         cudaFuncAttributeMaxDynamicSharedMemorySize, GEMM_SMEM);
    cudaFuncSetAttribute(gemm_bf16<1, __nv_bfloat16>,
                         cudaFuncAttributeMaxDynamicSharedMemorySize, GEMM_SMEM);
    cudaFuncSetAttribute(gemm_bf16<2, float>,
                         cudaFuncAttributeMaxDynamicSharedMemorySize, GEMM_SMEM);
    cudaFuncSetAttribute(attn_mma_kernel,
                         cudaFuncAttributeMaxDynamicSharedMemorySize, ATTN_SMEM);

    dim3 tb(32, 8);
    convT4_kernel<<<6912, tb>>>(w_qkv, wqkvT, w_proj, wprojT, w1, w1T, w2, w2T);   // 0
    ln_kernel<<<RB, 256>>>(x, ln1_g, ln1_b, h1b);                                   // 1
    gemm_bf16<0, __nv_bfloat16><<<dim3(3 * CC / BN, RB / BM), 256, GEMM_SMEM>>>(    // 2
        h1b, wqkvT, b_qkv, qkvb, RB, 3 * CC, CC, nullptr, nullptr);
    vtrans_kernel<<<dim3(NTOK / 32, DD / 32, 2 * HH), tb>>>(qkvb, vt);              // 3
    attn_mma_kernel<<<dim3(NTOK / QT, 2 * HH), 256, ATTN_SMEM>>>(qkvb, vt, mask, oatb); // 4
    gemm_bf16<2, float><<<dim3(CC / BN, RB / BM), 256, GEMM_SMEM>>>(                // 5
        oatb, wprojT, b_proj, x1, RB, CC, CC, x, ls1);
    ln_kernel<<<RB, 256>>>(x1, ln2_g, ln2_b, h1b);                                  // 6
    gemm_bf16<1, __nv_bfloat16><<<dim3(4 * CC / BN, RB / BM), 256, GEMM_SMEM>>>(    // 7
        h1b, w1T, b1, ffnb, RB, 4 * CC, CC, nullptr, nullptr);
    gemm_bf16<2, float><<<dim3(CC / BN, RB / BM), 256, GEMM_SMEM>>>(                // 8
        ffnb, w2T, b2, out, RB, CC, 4 * CC, x1, ls2);
}

// round 16
// speedup vs baseline: 1.0757x; 1.0065x over previous
#include <cuda_runtime.h>
#include <cuda_bf16.h>
#include <math.h>

// Problem constants
#define RB   4096   // B*N rows
#define CC   768
#define NTOK 2048
#define HH   12
#define DD   64

// ---------------- scratch (device globals: allocation-free) ----------------
__device__ __nv_bfloat16 d_h1b [RB * CC];
__device__ __nv_bfloat16 d_qkvb[RB * 3 * CC];
__device__ __nv_bfloat16 d_vt  [2 * HH * DD * NTOK];
__device__ __nv_bfloat16 d_oatb[RB * CC];
__device__ float         d_x1  [RB * CC];
__device__ __nv_bfloat16 d_ffnb[RB * 4 * CC];
__device__ float         d_fc2p[2 * RB * CC];
__device__ __nv_bfloat16 d_wqkvT[3 * CC * CC];
__device__ __nv_bfloat16 d_wprojT[CC * CC];
__device__ __nv_bfloat16 d_w1T[4 * CC * CC];
__device__ __nv_bfloat16 d_w2T[CC * 4 * CC];

__device__ __forceinline__ unsigned bf2_as_u32(__nv_bfloat162 v) {
    union { __nv_bfloat162 h; unsigned u; } cvt;
    cvt.h = v;
    return cvt.u;
}

// ---------------- batched fp32 -> bf16 transpose of all 4 weights ------------
__global__ void convT4_kernel(const float* __restrict__ s0, __nv_bfloat16* __restrict__ dq,
                              const float* __restrict__ s1, __nv_bfloat16* __restrict__ dp,
                              const float* __restrict__ s2, __nv_bfloat16* __restrict__ d1,
                              const float* __restrict__ s3, __nv_bfloat16* __restrict__ d2) {
    int bid = blockIdx.x;
    const float* src; __nv_bfloat16* dst; int R, Cc, local;
    if (bid < 1728)      { src = s0; dst = dq; R = CC;     Cc = 3 * CC; local = bid; }
    else if (bid < 2304) { src = s1; dst = dp; R = CC;     Cc = CC;     local = bid - 1728; }
    else if (bid < 4608) { src = s2; dst = d1; R = CC;     Cc = 4 * CC; local = bid - 2304; }
    else                 { src = s3; dst = d2; R = 4 * CC; Cc = CC;     local = bid - 4608; }
    int ncx = Cc / 32;
    int bx = (local % ncx) * 32, by = (local / ncx) * 32;

    __shared__ float tile[32][33];
    int tx = threadIdx.x, ty = threadIdx.y;
#pragma unroll
    for (int i = 0; i < 4; i++)
        tile[ty + i * 8][tx] = src[(size_t)(by + ty + i * 8) * Cc + bx + tx];
    __syncthreads();
#pragma unroll
    for (int i = 0; i < 4; i++)
        dst[(size_t)(bx + ty + i * 8) * R + by + tx] = __float2bfloat16(tile[tx][ty + i * 8]);
}

// ---------------- V transpose: qkvb V slice -> vt[bh][d][tok] ---------------
__global__ void vtrans_kernel(const __nv_bfloat16* __restrict__ qkvb,
                              __nv_bfloat16* __restrict__ vt) {
    __shared__ __nv_bfloat16 tile[32][33];
    int tok0 = blockIdx.x * 32, d0 = blockIdx.y * 32, bh = blockIdx.z;
    int b = bh / HH, h = bh % HH;
    int tx = threadIdx.x, ty = threadIdx.y;
#pragma unroll
    for (int i = 0; i < 4; i++) {
        int tok = tok0 + ty + i * 8;
        tile[ty + i * 8][tx] =
            qkvb[(size_t)(b * NTOK + tok) * (3 * CC) + 2 * CC + h * DD + d0 + tx];
    }
    __syncthreads();
#pragma unroll
    for (int i = 0; i < 4; i++) {
        int d = d0 + ty + i * 8;
        vt[(size_t)(bh * DD + d) * NTOK + tok0 + tx] = tile[tx][ty + i * 8];
    }
}

// ---------------- LayerNorm: one block per row, bf16 out ----------------
__global__ void ln_kernel(const float* __restrict__ x, const float* __restrict__ g,
                          const float* __restrict__ b, __nv_bfloat16* __restrict__ out) {
    int row = blockIdx.x, t = threadIdx.x;
    const float* xr = x + (size_t)row * CC;
    float v0 = xr[t], v1 = xr[t + 256], v2 = xr[t + 512];
    float s  = v0 + v1 + v2;
    float ss = v0 * v0 + v1 * v1 + v2 * v2;
#pragma unroll
    for (int o = 16; o > 0; o >>= 1) {
        s  += __shfl_xor_sync(0xffffffffu, s,  o);
        ss += __shfl_xor_sync(0xffffffffu, ss, o);
    }
    __shared__ float rs[8], rss[8], sh_mu, sh_rstd;
    int w = t >> 5, lane = t & 31;
    if (!lane) { rs[w] = s; rss[w] = ss; }
    __syncthreads();
    if (t == 0) {
        float S = 0.f, SS = 0.f;
#pragma unroll
        for (int i = 0; i < 8; i++) { S += rs[i]; SS += rss[i]; }
        float mu  = S * (1.0f / CC);
        float var = SS * (1.0f / CC) - mu * mu;
        sh_mu = mu; sh_rstd = rsqrtf(var + 1e-5f);
    }
    __syncthreads();
    float mu = sh_mu, rstd = sh_rstd;
    __nv_bfloat16* orow = out + (size_t)row * CC;
    orow[t]       = __float2bfloat16((v0 - mu) * rstd * g[t]       + b[t]);
    orow[t + 256] = __float2bfloat16((v1 - mu) * rstd * g[t + 256] + b[t + 256]);
    orow[t + 512] = __float2bfloat16((v2 - mu) * rstd * g[t + 512] + b[t + 512]);
}

// ---------------- combine kernel for FC2 split-K -----------------------------
// out = x1 + (p0 + p1 + bias) * ls
__global__ void combine_fc2(const float* __restrict__ p, const float* __restrict__ x1,
                            const float* __restrict__ bias, const float* __restrict__ ls,
                            float* __restrict__ out) {
    int idx = blockIdx.x * 256 + threadIdx.x;          // float4 index
    int col4 = idx % (CC / 4);
    float4 a = ((const float4*)p)[idx];
    float4 b = ((const float4*)p)[idx + RB * CC / 4];
    float4 r = ((const float4*)x1)[idx];
    float4 bs = ((const float4*)bias)[col4];
    float4 l = ((const float4*)ls)[col4];
    float4 o;
    o.x = r.x + (a.x + b.x + bs.x) * l.x;
    o.y = r.y + (a.y + b.y + bs.y) * l.y;
    o.z = r.z + (a.z + b.z + bs.z) * l.z;
    o.w = r.w + (a.w + b.w + bs.w) * l.w;
    ((float4*)out)[idx] = o;
}

// ---------------- primitives ----------------
__device__ __forceinline__ void cpa16_r(unsigned saddr, const void* gmem) {
    asm volatile("cp.async.cg.shared.global [%0], [%1], 16;\n" :: "r"(saddr), "l"(gmem));
}
__device__ __forceinline__ void cp_commit() { asm volatile("cp.async.commit_group;\n"); }
__device__ __forceinline__ void cp_wait1()  { asm volatile("cp.async.wait_group 1;\n"); }
__device__ __forceinline__ void cp_wait0()  { asm volatile("cp.async.wait_group 0;\n"); }

__device__ __forceinline__ unsigned sw128(unsigned off) {
    return off ^ ((off >> 3) & 0x70);
}

__device__ __forceinline__ void ldsm_x4(unsigned& r0, unsigned& r1, unsigned& r2, unsigned& r3,
                                        unsigned addr) {
    asm volatile("ldmatrix.sync.aligned.m8n8.x4.shared.b16 {%0,%1,%2,%3}, [%4];\n"
                 : "=r"(r0), "=r"(r1), "=r"(r2), "=r"(r3) : "r"(addr));
}

__device__ __forceinline__ void mma_bf16(float& c0, float& c1, float& c2, float& c3,
                                         unsigned a0, unsigned a1, unsigned a2, unsigned a3,
                                         unsigned b0, unsigned b1) {
    asm volatile(
        "mma.sync.aligned.m16n8k16.row.col.f32.bf16.bf16.f32 "
        "{%0,%1,%2,%3}, {%4,%5,%6,%7}, {%8,%9}, {%0,%1,%2,%3};\n"
        : "+f"(c0), "+f"(c1), "+f"(c2), "+f"(c3)
        : "r"(a0), "r"(a1), "r"(a2), "r"(a3), "r"(b0), "r"(b1));
}

// ---------------- bf16 GEMM (NT): C = A[M,K] @ Bt[N,K]^T -------------------
// 128x128 CTA tile, BK=64, 3-stage cp.async pipeline, ldmatrix fragments,
// XOR-swizzled smem (128B rows).   [byte-identical to the proven R15 version]
#define BM 128
#define BN 128
#define BK 64
#define STAGE_BYTES  (2 * BM * BK * 2)          // A + B per stage = 32KB
#define GEMM_SMEM    (3 * STAGE_BYTES)          // 96KB

template <int EPI, typename OutT>
__global__ __launch_bounds__(256)
void gemm_bf16(const __nv_bfloat16* __restrict__ A, const __nv_bfloat16* __restrict__ Bt,
               const float* __restrict__ bias, OutT* __restrict__ Cm,
               int M, int Nn, int K,
               const float* __restrict__ resid, const float* __restrict__ ls) {
    extern __shared__ __nv_bfloat16 smem[];
    unsigned smem_u32 = (unsigned)__cvta_generic_to_shared(smem);

    int t = threadIdx.x;
    int bm = blockIdx.y * BM, bn = blockIdx.x * BN;
    int w = t >> 5, lane = t & 31;
    int g = lane >> 2, t2 = (lane & 3) * 2;
    int wm = (w >> 2) * 64, wn = (w & 3) * 32;

    int l7 = lane & 7, mmat = lane >> 3;
    unsigned a_row_base = (unsigned)(wm + (mmat & 1) * 8 + l7);
    unsigned a_khalf    = (unsigned)((mmat >> 1) * 16);
    unsigned b_row_base = (unsigned)(wn + (mmat >> 1) * 8 + l7);
    unsigned b_khalf    = (unsigned)((mmat & 1) * 16);

    float acc[4][4][4];
#pragma unroll
    for (int mi = 0; mi < 4; mi++)
#pragma unroll
        for (int ni = 0; ni < 4; ni++)
#pragma unroll
            for (int c = 0; c < 4; c++) acc[mi][ni][c] = 0.f;

    int nk = K / BK;

    auto load_tile = [&](int kt, int s) {
        unsigned abase = smem_u32 + (unsigned)(s * STAGE_BYTES);
        unsigned bbase = abase + (unsigned)(BM * BK * 2);
#pragma unroll
        for (int i = 0; i < 4; i++) {
            int idx = t + 256 * i;
            int row = idx >> 3, seg = idx & 7;
            unsigned off = sw128((unsigned)(row * 128 + seg * 16));
            const __nv_bfloat16* ap = A  + (size_t)(bm + row) * K + kt * BK + seg * 8;
            const __nv_bfloat16* bp = Bt + (size_t)(bn + row) * K + kt * BK + seg * 8;
            cpa16_r(abase + off, ap);
            cpa16_r(bbase + off, bp);
        }
    };

    load_tile(0, 0); cp_commit();
    load_tile(1, 1); cp_commit();

    for (int kt = 0; kt < nk; kt++) {
        int s = kt % 3;
        if (kt + 1 < nk) cp_wait1(); else cp_wait0();
        __syncthreads();
        if (kt + 2 < nk) {
            load_tile(kt + 2, (kt + 2) % 3);
            cp_commit();
        }

        unsigned abase = smem_u32 + (unsigned)(s * STAGE_BYTES);
        unsigned bbase = abase + (unsigned)(BM * BK * 2);

#pragma unroll
        for (int ks = 0; ks < 4; ks++) {
            unsigned af[4][4], bfr[4][2];
#pragma unroll
            for (int mi = 0; mi < 4; mi++) {
                unsigned off = sw128((a_row_base + mi * 16) * 128 + (unsigned)(ks * 32) + a_khalf);
                ldsm_x4(af[mi][0], af[mi][1], af[mi][2], af[mi][3], abase + off);
            }
#pragma unroll
            for (int p = 0; p < 2; p++) {
                unsigned off = sw128((b_row_base + p * 16) * 128 + (unsigned)(ks * 32) + b_khalf);
                unsigned r0, r1, r2, r3;
                ldsm_x4(r0, r1, r2, r3, bbase + off);
                bfr[2 * p][0] = r0;     bfr[2 * p][1] = r1;
                bfr[2 * p + 1][0] = r2; bfr[2 * p + 1][1] = r3;
            }
#pragma unroll
            for (int mi = 0; mi < 4; mi++)
#pragma unroll
                for (int ni = 0; ni < 4; ni++)
                    mma_bf16(acc[mi][ni][0], acc[mi][ni][1], acc[mi][ni][2], acc[mi][ni][3],
                             af[mi][0], af[mi][1], af[mi][2], af[mi][3],
                             bfr[ni][0], bfr[ni][1]);
        }
        __syncthreads();
    }

    // epilogue
#pragma unroll
    for (int mi = 0; mi < 4; mi++) {
#pragma unroll
        for (int half = 0; half < 2; half++) {
            int m = bm + wm + mi * 16 + g + half * 8;
#pragma unroll
            for (int ni = 0; ni < 4; ni++) {
                int col = bn + wn + ni * 8 + t2;
                float v0 = acc[mi][ni][half * 2 + 0] + bias[col];
                float v1 = acc[mi][ni][half * 2 + 1] + bias[col + 1];
                if (EPI == 1) {
                    v0 = 0.5f * v0 * (1.0f + erff(v0 * 0.70710678118654752f));
                    v1 = 0.5f * v1 * (1.0f + erff(v1 * 0.70710678118654752f));
                } else if (EPI == 2) {
                    const float* rp = resid + (size_t)m * Nn + col;
                    v0 = rp[0] + v0 * ls[col];
                    v1 = rp[1] + v1 * ls[col + 1];
                }
                OutT* cp = Cm + (size_t)m * Nn + col;
                if (sizeof(OutT) == 4) {
                    *(float2*)cp = make_float2(v0, v1);
                } else {
                    *(__nv_bfloat162*)cp = __floats2bfloat162_rn(v0, v1);
                }
            }
        }
    }
}

// ---------------- dedicated FC2 split-K=2 GEMM (compile-time strides) --------
// A[4096,3072] bf16, Bt[768,3072] bf16; slice z covers K range [z*1536,(z+1)*1536).
// Writes raw fp32 partials to p[z][m][n]. All strides compile-time constants.
#define F2K  (2 * CC)          // 1536 per slice
#define F2LD (4 * CC)          // 3072 row stride

__global__ __launch_bounds__(256)
void gemm_fc2k(const __nv_bfloat16* __restrict__ A, const __nv_bfloat16* __restrict__ Bt,
               float* __restrict__ P) {
    extern __shared__ __nv_bfloat16 smem[];
    unsigned smem_u32 = (unsigned)__cvta_generic_to_shared(smem);

    int t = threadIdx.x;
    int bm = blockIdx.y * BM, bn = blockIdx.x * BN;
    int kz = blockIdx.z;
    const __nv_bfloat16* Ab = A  + (size_t)kz * F2K;
    const __nv_bfloat16* Bb = Bt + (size_t)kz * F2K;
    float* Pb = P + (size_t)kz * RB * CC;

    int w = t >> 5, lane = t & 31;
    int g = lane >> 2, t2 = (lane & 3) * 2;
    int wm = (w >> 2) * 64, wn = (w & 3) * 32;

    int l7 = lane & 7, mmat = lane >> 3;
    unsigned a_row_base = (unsigned)(wm + (mmat & 1) * 8 + l7);
    unsigned a_khalf    = (unsigned)((mmat >> 1) * 16);
    unsigned b_row_base = (unsigned)(wn + (mmat >> 1) * 8 + l7);
    unsigned b_khalf    = (unsigned)((mmat & 1) * 16);

    float acc[4][4][4];
#pragma unroll
    for (int mi = 0; mi < 4; mi++)
#pragma unroll
        for (int ni = 0; ni < 4; ni++)
#pragma unroll
            for (int c = 0; c < 4; c++) acc[mi][ni][c] = 0.f;

    const int nk = F2K / BK;   // 24

    auto load_tile = [&](int kt, int s) {
        unsigned abase = smem_u32 + (unsigned)(s * STAGE_BYTES);
        unsigned bbase = abase + (unsigned)(BM * BK * 2);
#pragma unroll
        for (int i = 0; i < 4; i++) {
            int idx = t + 256 * i;
            int row = idx >> 3, seg = idx & 7;
            unsigned off = sw128((unsigned)(row * 128 + seg * 16));
            const __nv_bfloat16* ap = Ab + (size_t)(bm + row) * F2LD + kt * BK + seg * 8;
            const __nv_bfloat16* bp = Bb + (size_t)(bn + row) * F2LD + kt * BK + seg * 8;
            cpa16_r(abase + off, ap);
            cpa16_r(bbase + off, bp);
        }
    };

    load_tile(0, 0); cp_commit();
    load_tile(1, 1); cp_commit();

    for (int kt = 0; kt < nk; kt++) {
        int s = kt % 3;
        if (kt + 1 < nk) cp_wait1(); else cp_wait0();
        __syncthreads();
        if (kt + 2 < nk) {
            load_tile(kt + 2, (kt + 2) % 3);
            cp_commit();
        }

        unsigned abase = smem_u32 + (unsigned)(s * STAGE_BYTES);
        unsigned bbase = abase + (unsigned)(BM * BK * 2);

#pragma unroll
        for (int ks = 0; ks < 4; ks++) {
            unsigned af[4][4], bfr[4][2];
#pragma unroll
            for (int mi = 0; mi < 4; mi++) {
                unsigned off = sw128((a_row_base + mi * 16) * 128 + (unsigned)(ks * 32) + a_khalf);
                ldsm_x4(af[mi][0], af[mi][1], af[mi][2], af[mi][3], abase + off);
            }
#pragma unroll
            for (int p = 0; p < 2; p++) {
                unsigned off = sw128((b_row_base + p * 16) * 128 + (unsigned)(ks * 32) + b_khalf);
                unsigned r0, r1, r2, r3;
                ldsm_x4(r0, r1, r2, r3, bbase + off);
                bfr[2 * p][0] = r0;     bfr[2 * p][1] = r1;
                bfr[2 * p + 1][0] = r2; bfr[2 * p + 1][1] = r3;
            }
#pragma unroll
            for (int mi = 0; mi < 4; mi++)
#pragma unroll
                for (int ni = 0; ni < 4; ni++)
                    mma_bf16(acc[mi][ni][0], acc[mi][ni][1], acc[mi][ni][2], acc[mi][ni][3],
                             af[mi][0], af[mi][1], af[mi][2], af[mi][3],
                             bfr[ni][0], bfr[ni][1]);
        }
        __syncthreads();
    }

    // raw fp32 partial store
#pragma unroll
    for (int mi = 0; mi < 4; mi++) {
#pragma unroll
        for (int half = 0; half < 2; half++) {
            int m = bm + wm + mi * 16 + g + half * 8;
#pragma unroll
            for (int ni = 0; ni < 4; ni++) {
                int col = bn + wn + ni * 8 + t2;
                *(float2*)(Pb + (size_t)m * CC + col) =
                    make_float2(acc[mi][ni][half * 2 + 0], acc[mi][ni][half * 2 + 1]);
            }
        }
    }
}

// ---------------- bf16 flash attention: cp.async K/V + ldmatrix fragments ----
#define QT 128
#define KT 64
#define AST 72
#define ATTN_SMEM ((QT + 4 * KT) * AST * 2)    // Q + 2xK + 2xV = 55296 B

__global__ __launch_bounds__(256)
void attn_mma_kernel(const __nv_bfloat16* __restrict__ qkvb,
                     const __nv_bfloat16* __restrict__ vt,
                     const unsigned char* __restrict__ mask,
                     __nv_bfloat16* __restrict__ o) {
    extern __shared__ __nv_bfloat16 ash[];
    unsigned Qu = (unsigned)__cvta_generic_to_shared(ash);
    unsigned Ku = Qu + QT * AST * 2;
    unsigned Vu = Ku + 2 * KT * AST * 2;

    int t = threadIdx.x;
    int w = t >> 5, lane = t & 31;
    int g = lane >> 2, t2 = (lane & 3) * 2;
    int qt = blockIdx.x, bh = blockIdx.y;
    int b = bh / HH, head = bh % HH;
    int qbase = qt * QT;
    size_t base = (size_t)b * NTOK;

    int l7 = lane & 7, mmat = lane >> 3;
    unsigned a_base = Qu +
        (unsigned)(((w * 16 + (mmat & 1) * 8 + l7) * AST + (mmat >> 1) * 8) * 2);
    unsigned kv_off = (unsigned)((((mmat >> 1) * 8 + l7) * AST + (mmat & 1) * 8) * 2);

    auto load_kv = [&](int kt2, int buf) {
        int kbase = kt2 * KT;
        unsigned kb = Ku + (unsigned)(buf * KT * AST * 2);
        unsigned vb = Vu + (unsigned)(buf * KT * AST * 2);
#pragma unroll
        for (int i = 0; i < 2; i++) {
            int id = t + 256 * i;
            int row = id >> 3, seg = id & 7;
            cpa16_r(kb + (unsigned)(row * AST * 2 + seg * 16),
                    qkvb + (base + kbase + row) * (size_t)(3 * CC) + CC + head * DD + seg * 8);
            cpa16_r(vb + (unsigned)(row * AST * 2 + seg * 16),
                    vt + (size_t)(bh * DD + row) * NTOK + kbase + seg * 8);
        }
        cp_commit();
    };

#pragma unroll
    for (int i = 0; i < 4; i++) {
        int id = t + 256 * i;
        int row = id >> 3, seg = id & 7;
        cpa16_r(Qu + (unsigned)(row * AST * 2 + seg * 16),
                qkvb + (base + qbase + row) * (size_t)(3 * CC) + head * DD + seg * 8);
    }
    load_kv(0, 0);

    int r0 = w * 16 + g;
    const unsigned char* mrow0 = mask + (size_t)(qbase + r0) * NTOK;
    const unsigned char* mrow1 = mrow0 + (size_t)8 * NTOK;

    float m0 = -1e30f, m1 = -1e30f, l0 = 0.f, l1 = 0.f;
    float oacc[8][4];
#pragma unroll
    for (int nd = 0; nd < 8; nd++)
#pragma unroll
        for (int c = 0; c < 4; c++) oacc[nd][c] = 0.f;

    for (int kt2 = 0; kt2 < NTOK / KT; kt2++) {
        int buf = kt2 & 1;
        int kbase = kt2 * KT;
        cp_wait0();
        __syncthreads();
        if (kt2 + 1 < NTOK / KT) load_kv(kt2 + 1, buf ^ 1);

        unsigned Kbuf = Ku + (unsigned)(buf * KT * AST * 2);
        unsigned Vbuf = Vu + (unsigned)(buf * KT * AST * 2);

        float sacc[8][4];
#pragma unroll
        for (int nb = 0; nb < 8; nb++)
#pragma unroll
            for (int c = 0; c < 4; c++) sacc[nb][c] = 0.f;
#pragma unroll
        for (int ds = 0; ds < 4; ds++) {
            unsigned a0, a1, a2, a3;
            ldsm_x4(a0, a1, a2, a3, a_base + (unsigned)(ds * 32));
#pragma unroll
            for (int p = 0; p < 4; p++) {
                unsigned r0v, r1v, r2v, r3v;
                ldsm_x4(r0v, r1v, r2v, r3v,
                        Kbuf + (unsigned)(p * 16 * AST * 2) + kv_off + (unsigned)(ds * 32));
                mma_bf16(sacc[2 * p][0], sacc[2 * p][1], sacc[2 * p][2], sacc[2 * p][3],
                         a0, a1, a2, a3, r0v, r1v);
                mma_bf16(sacc[2 * p + 1][0], sacc[2 * p + 1][1],
                         sacc[2 * p + 1][2], sacc[2 * p + 1][3],
                         a0, a1, a2, a3, r2v, r3v);
            }
        }

        float rmax0 = -1e30f, rmax1 = -1e30f;
#pragma unroll
        for (int nb = 0; nb < 8; nb++) {
            uchar2 mq0 = *(const uchar2*)(mrow0 + kbase + nb * 8 + t2);
            uchar2 mq1 = *(const uchar2*)(mrow1 + kbase + nb * 8 + t2);
            float s00 = mq0.x ? -1e30f : sacc[nb][0] * 0.125f;
            float s01 = mq0.y ? -1e30f : sacc[nb][1] * 0.125f;
            float s10 = mq1.x ? -1e30f : sacc[nb][2] * 0.125f;
            float s11 = mq1.y ? -1e30f : sacc[nb][3] * 0.125f;
            sacc[nb][0] = s00; sacc[nb][1] = s01; sacc[nb][2] = s10; sacc[nb][3] = s11;
            rmax0 = fmaxf(rmax0, fmaxf(s00, s01));
            rmax1 = fmaxf(rmax1, fmaxf(s10, s11));
        }
#pragma unroll
        for (int off = 1; off < 4; off <<= 1) {
            rmax0 = fmaxf(rmax0, __shfl_xor_sync(0xffffffffu, rmax0, off));
            rmax1 = fmaxf(rmax1, __shfl_xor_sync(0xffffffffu, rmax1, off));
        }
        float mn0 = fmaxf(m0, rmax0), mn1 = fmaxf(m1, rmax1);
        float al0 = __expf(m0 - mn0), al1 = __expf(m1 - mn1);
        m0 = mn0; m1 = mn1;

        unsigned pr0[8], pr1[8];
        float rs0 = 0.f, rs1 = 0.f;
#pragma unroll
        for (int nb = 0; nb < 8; nb++) {
            float p00 = __expf(sacc[nb][0] - mn0);
            float p01 = __expf(sacc[nb][1] - mn0);
            float p10 = __expf(sacc[nb][2] - mn1);
            float p11 = __expf(sacc[nb][3] - mn1);
            rs0 += p00 + p01; rs1 += p10 + p11;
            pr0[nb] = bf2_as_u32(__floats2bfloat162_rn(p00, p01));
            pr1[nb] = bf2_as_u32(__floats2bfloat162_rn(p10, p11));
        }
#pragma unroll
        for (int off = 1; off < 4; off <<= 1) {
            rs0 += __shfl_xor_sync(0xffffffffu, rs0, off);
            rs1 += __shfl_xor_sync(0xffffffffu, rs1, off);
        }
        l0 = l0 * al0 + rs0;
        l1 = l1 * al1 + rs1;

#pragma unroll
        for (int nd = 0; nd < 8; nd++) {
            oacc[nd][0] *= al0; oacc[nd][1] *= al0;
            oacc[nd][2] *= al1; oacc[nd][3] *= al1;
        }
#pragma unroll
        for (int kb = 0; kb < 4; kb++) {
            unsigned a0 = pr0[2 * kb],     a1 = pr1[2 * kb];
            unsigned a2 = pr0[2 * kb + 1], a3 = pr1[2 * kb + 1];
#pragma unroll
            for (int p = 0; p < 4; p++) {
                unsigned r0v, r1v, r2v, r3v;
                ldsm_x4(r0v, r1v, r2v, r3v,
                        Vbuf + (unsigned)(p * 16 * AST * 2) + kv_off + (unsigned)(kb * 32));
                mma_bf16(oacc[2 * p][0], oacc[2 * p][1], oacc[2 * p][2], oacc[2 * p][3],
                         a0, a1, a2, a3, r0v, r1v);
                mma_bf16(oacc[2 * p + 1][0], oacc[2 * p + 1][1],
                         oacc[2 * p + 1][2], oacc[2 * p + 1][3],
                         a0, a1, a2, a3, r2v, r3v);
            }
        }
    }

    float inv0 = 1.0f / l0, inv1 = 1.0f / l1;
    __nv_bfloat16* op0 = o + (base + qbase + r0) * (size_t)CC + head * DD;
    __nv_bfloat16* op1 = op0 + (size_t)8 * CC;
#pragma unroll
    for (int nd = 0; nd < 8; nd++) {
        *(__nv_bfloat162*)(op0 + nd * 8 + t2) =
            __floats2bfloat162_rn(oacc[nd][0] * inv0, oacc[nd][1] * inv0);
        *(__nv_bfloat162*)(op1 + nd * 8 + t2) =
            __floats2bfloat162_rn(oacc[nd][2] * inv1, oacc[nd][3] * inv1);
    }
}

// ---------------- launch ----------------
extern "C" void kernel_launch(void* const* d_in, const int* in_sizes, int n_in,
                              void* d_out, int out_size) {
    (void)in_sizes; (void)n_in; (void)out_size;
    const float* x            = (const float*)d_in[0];
    const unsigned char* mask = (const unsigned char*)d_in[1];
    const float* ln1_g  = (const float*)d_in[2];
    const float* ln1_b  = (const float*)d_in[3];
    const float* w_qkv  = (const float*)d_in[4];
    const float* b_qkv  = (const float*)d_in[5];
    const float* w_proj = (const float*)d_in[6];
    const float* b_proj = (const float*)d_in[7];
    const float* ls1    = (const float*)d_in[8];
    const float* ln2_g  = (const float*)d_in[9];
    const float* ln2_b  = (const float*)d_in[10];
    const float* w1     = (const float*)d_in[11];
    const float* b1     = (const float*)d_in[12];
    const float* w2     = (const float*)d_in[13];
    const float* b2     = (const float*)d_in[14];
    const float* ls2    = (const float*)d_in[15];
    float* out = (float*)d_out;

    __nv_bfloat16 *h1b, *qkvb, *vt, *oatb, *ffnb, *wqkvT, *wprojT, *w1T, *w2T;
    float *x1, *fc2p;
    cudaGetSymbolAddress((void**)&h1b,   d_h1b);
    cudaGetSymbolAddress((void**)&qkvb,  d_qkvb);
    cudaGetSymbolAddress((void**)&vt,    d_vt);
    cudaGetSymbolAddress((void**)&oatb,  d_oatb);
    cudaGetSymbolAddress((void**)&x1,    d_x1);
    cudaGetSymbolAddress((void**)&ffnb,  d_ffnb);
    cudaGetSymbolAddress((void**)&fc2p,  d_fc2p);
    cudaGetSymbolAddress((void**)&wqkvT, d_wqkvT);
    cudaGetSymbolAddress((void**)&wprojT,d_wprojT);
    cudaGetSymbolAddress((void**)&w1T,   d_w1T);
    cudaGetSymbolAddress((void**)&w2T,   d_w2T);

    cudaFuncSetAttribute(gemm_bf16<0, __nv_bfloat16>,
                         cudaFuncAttributeMaxDynamicSharedMemorySize, GEMM_SMEM);
    cudaFuncSetAttribute(gemm_bf16<1, __nv_bfloat16>,
                         cudaFuncAttributeMaxDynamicSharedMemorySize, GEMM_SMEM);
    cudaFuncSetAttribute(gemm_bf16<2, float>,
                         cudaFuncAttributeMaxDynamicSharedMemorySize, GEMM_SMEM);
    cudaFuncSetAttribute(gemm_fc2k,
                         cudaFuncAttributeMaxDynamicSharedMemorySize, GEMM_SMEM);
    cudaFuncSetAttribute(attn_mma_kernel,
                         cudaFuncAttributeMaxDynamicSharedMemorySize, ATTN_SMEM);

    dim3 tb(32, 8);
    convT4_kernel<<<6912, tb>>>(w_qkv, wqkvT, w_proj, wprojT, w1, w1T, w2, w2T);   // 0
    ln_kernel<<<RB, 256>>>(x, ln1_g, ln1_b, h1b);                                   // 1
    gemm_bf16<0, __nv_bfloat16><<<dim3(3 * CC / BN, RB / BM), 256, GEMM_SMEM>>>(    // 2
        h1b, wqkvT, b_qkv, qkvb, RB, 3 * CC, CC, nullptr, nullptr);
    vtrans_kernel<<<dim3(NTOK / 32, DD / 32, 2 * HH), tb>>>(qkvb, vt);              // 3
    attn_mma_kernel<<<dim3(NTOK / QT, 2 * HH), 256, ATTN_SMEM>>>(qkvb, vt, mask, oatb); // 4
    gemm_bf16<2, float><<<dim3(CC / BN, RB / BM), 256, GEMM_SMEM>>>(                // 5
        oatb, wprojT, b_proj, x1, RB, CC, CC, x, ls1);
    ln_kernel<<<RB, 256>>>(x1, ln2_g, ln2_b, h1b);                                  // 6
    gemm_bf16<1, __nv_bfloat16><<<dim3(4 * CC / BN, RB / BM), 256, GEMM_SMEM>>>(    // 7
        h1b, w1T, b1, ffnb, RB, 4 * CC, CC, nullptr, nullptr);
    gemm_fc2k<<<dim3(CC / BN, RB / BM, 2), 256, GEMM_SMEM>>>(ffnb, w2T, fc2p);      // 8
    combine_fc2<<<RB * CC / 4 / 256, 256>>>(fc2p, x1, b2, ls2, out);                // 9
}

// round 17
// speedup vs baseline: 1.0802x; 1.0041x over previous
#include <cuda_runtime.h>
#include <cuda_bf16.h>
#include <math.h>

// Problem constants
#define RB   4096   // B*N rows
#define CC   768
#define NTOK 2048
#define HH   12
#define DD   64

// ---------------- scratch (device globals: allocation-free) ----------------
__device__ __nv_bfloat16 d_h1b [RB * CC];
__device__ __nv_bfloat16 d_qkvb[RB * 3 * CC];
__device__ __nv_bfloat16 d_vt  [2 * HH * DD * NTOK];
__device__ __nv_bfloat16 d_oatb[RB * CC];
__device__ float         d_x1  [RB * CC];
__device__ __nv_bfloat16 d_ffnb[RB * 4 * CC];
__device__ float         d_fc2p[2 * RB * CC];
__device__ __nv_bfloat16 d_wqkvT[3 * CC * CC];
__device__ __nv_bfloat16 d_wprojT[CC * CC];
__device__ __nv_bfloat16 d_w1T[4 * CC * CC];
__device__ __nv_bfloat16 d_w2T[CC * 4 * CC];

__device__ __forceinline__ unsigned bf2_as_u32(__nv_bfloat162 v) {
    union { __nv_bfloat162 h; unsigned u; } cvt;
    cvt.h = v;
    return cvt.u;
}

// ---------------- batched fp32 -> bf16 transpose of all 4 weights ------------
__global__ void convT4_kernel(const float* __restrict__ s0, __nv_bfloat16* __restrict__ dq,
                              const float* __restrict__ s1, __nv_bfloat16* __restrict__ dp,
                              const float* __restrict__ s2, __nv_bfloat16* __restrict__ d1,
                              const float* __restrict__ s3, __nv_bfloat16* __restrict__ d2) {
    int bid = blockIdx.x;
    const float* src; __nv_bfloat16* dst; int R, Cc, local;
    if (bid < 1728)      { src = s0; dst = dq; R = CC;     Cc = 3 * CC; local = bid; }
    else if (bid < 2304) { src = s1; dst = dp; R = CC;     Cc = CC;     local = bid - 1728; }
    else if (bid < 4608) { src = s2; dst = d1; R = CC;     Cc = 4 * CC; local = bid - 2304; }
    else                 { src = s3; dst = d2; R = 4 * CC; Cc = CC;     local = bid - 4608; }
    int ncx = Cc / 32;
    int bx = (local % ncx) * 32, by = (local / ncx) * 32;

    __shared__ float tile[32][33];
    int tx = threadIdx.x, ty = threadIdx.y;
#pragma unroll
    for (int i = 0; i < 4; i++)
        tile[ty + i * 8][tx] = src[(size_t)(by + ty + i * 8) * Cc + bx + tx];
    __syncthreads();
#pragma unroll
    for (int i = 0; i < 4; i++)
        dst[(size_t)(bx + ty + i * 8) * R + by + tx] = __float2bfloat16(tile[tx][ty + i * 8]);
}

// ---------------- V transpose: qkvb V slice -> vt[bh][d][tok] ---------------
__global__ void vtrans_kernel(const __nv_bfloat16* __restrict__ qkvb,
                              __nv_bfloat16* __restrict__ vt) {
    __shared__ __nv_bfloat16 tile[32][33];
    int tok0 = blockIdx.x * 32, d0 = blockIdx.y * 32, bh = blockIdx.z;
    int b = bh / HH, h = bh % HH;
    int tx = threadIdx.x, ty = threadIdx.y;
#pragma unroll
    for (int i = 0; i < 4; i++) {
        int tok = tok0 + ty + i * 8;
        tile[ty + i * 8][tx] =
            qkvb[(size_t)(b * NTOK + tok) * (3 * CC) + 2 * CC + h * DD + d0 + tx];
    }
    __syncthreads();
#pragma unroll
    for (int i = 0; i < 4; i++) {
        int d = d0 + ty + i * 8;
        vt[(size_t)(bh * DD + d) * NTOK + tok0 + tx] = tile[tx][ty + i * 8];
    }
}

// ---------------- LayerNorm: one block per row, bf16 out ----------------
__global__ void ln_kernel(const float* __restrict__ x, const float* __restrict__ g,
                          const float* __restrict__ b, __nv_bfloat16* __restrict__ out) {
    int row = blockIdx.x, t = threadIdx.x;
    const float* xr = x + (size_t)row * CC;
    float v0 = xr[t], v1 = xr[t + 256], v2 = xr[t + 512];
    float s  = v0 + v1 + v2;
    float ss = v0 * v0 + v1 * v1 + v2 * v2;
#pragma unroll
    for (int o = 16; o > 0; o >>= 1) {
        s  += __shfl_xor_sync(0xffffffffu, s,  o);
        ss += __shfl_xor_sync(0xffffffffu, ss, o);
    }
    __shared__ float rs[8], rss[8], sh_mu, sh_rstd;
    int w = t >> 5, lane = t & 31;
    if (!lane) { rs[w] = s; rss[w] = ss; }
    __syncthreads();
    if (t == 0) {
        float S = 0.f, SS = 0.f;
#pragma unroll
        for (int i = 0; i < 8; i++) { S += rs[i]; SS += rss[i]; }
        float mu  = S * (1.0f / CC);
        float var = SS * (1.0f / CC) - mu * mu;
        sh_mu = mu; sh_rstd = rsqrtf(var + 1e-5f);
    }
    __syncthreads();
    float mu = sh_mu, rstd = sh_rstd;
    __nv_bfloat16* orow = out + (size_t)row * CC;
    orow[t]       = __float2bfloat16((v0 - mu) * rstd * g[t]       + b[t]);
    orow[t + 256] = __float2bfloat16((v1 - mu) * rstd * g[t + 256] + b[t + 256]);
    orow[t + 512] = __float2bfloat16((v2 - mu) * rstd * g[t + 512] + b[t + 512]);
}

// ---------------- combine kernel for FC2 split-K -----------------------------
__global__ void combine_fc2(const float* __restrict__ p, const float* __restrict__ x1,
                            const float* __restrict__ bias, const float* __restrict__ ls,
                            float* __restrict__ out) {
    int idx = blockIdx.x * 256 + threadIdx.x;          // float4 index
    int col4 = idx % (CC / 4);
    float4 a = ((const float4*)p)[idx];
    float4 b = ((const float4*)p)[idx + RB * CC / 4];
    float4 r = ((const float4*)x1)[idx];
    float4 bs = ((const float4*)bias)[col4];
    float4 l = ((const float4*)ls)[col4];
    float4 o;
    o.x = r.x + (a.x + b.x + bs.x) * l.x;
    o.y = r.y + (a.y + b.y + bs.y) * l.y;
    o.z = r.z + (a.z + b.z + bs.z) * l.z;
    o.w = r.w + (a.w + b.w + bs.w) * l.w;
    ((float4*)out)[idx] = o;
}

// ---------------- primitives ----------------
__device__ __forceinline__ void cpa16_r(unsigned saddr, const void* gmem) {
    asm volatile("cp.async.cg.shared.global [%0], [%1], 16;\n" :: "r"(saddr), "l"(gmem));
}
__device__ __forceinline__ void cp_commit() { asm volatile("cp.async.commit_group;\n"); }
__device__ __forceinline__ void cp_wait1()  { asm volatile("cp.async.wait_group 1;\n"); }
__device__ __forceinline__ void cp_wait0()  { asm volatile("cp.async.wait_group 0;\n"); }

__device__ __forceinline__ unsigned sw128(unsigned off) {
    return off ^ ((off >> 3) & 0x70);
}

__device__ __forceinline__ void ldsm_x4(unsigned& r0, unsigned& r1, unsigned& r2, unsigned& r3,
                                        unsigned addr) {
    asm volatile("ldmatrix.sync.aligned.m8n8.x4.shared.b16 {%0,%1,%2,%3}, [%4];\n"
                 : "=r"(r0), "=r"(r1), "=r"(r2), "=r"(r3) : "r"(addr));
}

__device__ __forceinline__ void mma_bf16(float& c0, float& c1, float& c2, float& c3,
                                         unsigned a0, unsigned a1, unsigned a2, unsigned a3,
                                         unsigned b0, unsigned b1) {
    asm volatile(
        "mma.sync.aligned.m16n8k16.row.col.f32.bf16.bf16.f32 "
        "{%0,%1,%2,%3}, {%4,%5,%6,%7}, {%8,%9}, {%0,%1,%2,%3};\n"
        : "+f"(c0), "+f"(c1), "+f"(c2), "+f"(c3)
        : "r"(a0), "r"(a1), "r"(a2), "r"(a3), "r"(b0), "r"(b1));
}

// ---------------- bf16 GEMM (NT): C = A[M,K] @ Bt[N,K]^T -------------------
#define BM 128
#define BN 128
#define BK 64
#define STAGE_BYTES  (2 * BM * BK * 2)          // A + B per stage = 32KB
#define GEMM_SMEM    (3 * STAGE_BYTES)          // 96KB

template <int EPI, typename OutT>
__global__ __launch_bounds__(256)
void gemm_bf16(const __nv_bfloat16* __restrict__ A, const __nv_bfloat16* __restrict__ Bt,
               const float* __restrict__ bias, OutT* __restrict__ Cm,
               int M, int Nn, int K,
               const float* __restrict__ resid, const float* __restrict__ ls) {
    extern __shared__ __nv_bfloat16 smem[];
    unsigned smem_u32 = (unsigned)__cvta_generic_to_shared(smem);

    int t = threadIdx.x;
    int bm = blockIdx.y * BM, bn = blockIdx.x * BN;
    int w = t >> 5, lane = t & 31;
    int g = lane >> 2, t2 = (lane & 3) * 2;
    int wm = (w >> 2) * 64, wn = (w & 3) * 32;

    int l7 = lane & 7, mmat = lane >> 3;
    unsigned a_row_base = (unsigned)(wm + (mmat & 1) * 8 + l7);
    unsigned a_khalf    = (unsigned)((mmat >> 1) * 16);
    unsigned b_row_base = (unsigned)(wn + (mmat >> 1) * 8 + l7);
    unsigned b_khalf    = (unsigned)((mmat & 1) * 16);

    float acc[4][4][4];
#pragma unroll
    for (int mi = 0; mi < 4; mi++)
#pragma unroll
        for (int ni = 0; ni < 4; ni++)
#pragma unroll
            for (int c = 0; c < 4; c++) acc[mi][ni][c] = 0.f;

    int nk = K / BK;

    auto load_tile = [&](int kt, int s) {
        unsigned abase = smem_u32 + (unsigned)(s * STAGE_BYTES);
        unsigned bbase = abase + (unsigned)(BM * BK * 2);
#pragma unroll
        for (int i = 0; i < 4; i++) {
            int idx = t + 256 * i;
            int row = idx >> 3, seg = idx & 7;
            unsigned off = sw128((unsigned)(row * 128 + seg * 16));
            const __nv_bfloat16* ap = A  + (size_t)(bm + row) * K + kt * BK + seg * 8;
            const __nv_bfloat16* bp = Bt + (size_t)(bn + row) * K + kt * BK + seg * 8;
            cpa16_r(abase + off, ap);
            cpa16_r(bbase + off, bp);
        }
    };

    load_tile(0, 0); cp_commit();
    load_tile(1, 1); cp_commit();

    for (int kt = 0; kt < nk; kt++) {
        int s = kt % 3;
        if (kt + 1 < nk) cp_wait1(); else cp_wait0();
        __syncthreads();
        if (kt + 2 < nk) {
            load_tile(kt + 2, (kt + 2) % 3);
            cp_commit();
        }

        unsigned abase = smem_u32 + (unsigned)(s * STAGE_BYTES);
        unsigned bbase = abase + (unsigned)(BM * BK * 2);

#pragma unroll
        for (int ks = 0; ks < 4; ks++) {
            unsigned af[4][4], bfr[4][2];
#pragma unroll
            for (int mi = 0; mi < 4; mi++) {
                unsigned off = sw128((a_row_base + mi * 16) * 128 + (unsigned)(ks * 32) + a_khalf);
                ldsm_x4(af[mi][0], af[mi][1], af[mi][2], af[mi][3], abase + off);
            }
#pragma unroll
            for (int p = 0; p < 2; p++) {
                unsigned off = sw128((b_row_base + p * 16) * 128 + (unsigned)(ks * 32) + b_khalf);
                unsigned r0, r1, r2, r3;
                ldsm_x4(r0, r1, r2, r3, bbase + off);
                bfr[2 * p][0] = r0;     bfr[2 * p][1] = r1;
                bfr[2 * p + 1][0] = r2; bfr[2 * p + 1][1] = r3;
            }
#pragma unroll
            for (int mi = 0; mi < 4; mi++)
#pragma unroll
                for (int ni = 0; ni < 4; ni++)
                    mma_bf16(acc[mi][ni][0], acc[mi][ni][1], acc[mi][ni][2], acc[mi][ni][3],
                             af[mi][0], af[mi][1], af[mi][2], af[mi][3],
                             bfr[ni][0], bfr[ni][1]);
        }
        __syncthreads();
    }

    // epilogue
#pragma unroll
    for (int mi = 0; mi < 4; mi++) {
#pragma unroll
        for (int half = 0; half < 2; half++) {
            int m = bm + wm + mi * 16 + g + half * 8;
#pragma unroll
            for (int ni = 0; ni < 4; ni++) {
                int col = bn + wn + ni * 8 + t2;
                float v0 = acc[mi][ni][half * 2 + 0] + bias[col];
                float v1 = acc[mi][ni][half * 2 + 1] + bias[col + 1];
                if (EPI == 1) {
                    v0 = 0.5f * v0 * (1.0f + erff(v0 * 0.70710678118654752f));
                    v1 = 0.5f * v1 * (1.0f + erff(v1 * 0.70710678118654752f));
                } else if (EPI == 2) {
                    const float* rp = resid + (size_t)m * Nn + col;
                    v0 = rp[0] + v0 * ls[col];
                    v1 = rp[1] + v1 * ls[col + 1];
                }
                OutT* cp = Cm + (size_t)m * Nn + col;
                if (sizeof(OutT) == 4) {
                    *(float2*)cp = make_float2(v0, v1);
                } else {
                    *(__nv_bfloat162*)cp = __floats2bfloat162_rn(v0, v1);
                }
            }
        }
    }
}

// ---------------- dedicated FC2 split-K=2 GEMM (compile-time strides) --------
#define F2K  (2 * CC)          // 1536 per slice
#define F2LD (4 * CC)          // 3072 row stride

__global__ __launch_bounds__(256)
void gemm_fc2k(const __nv_bfloat16* __restrict__ A, const __nv_bfloat16* __restrict__ Bt,
               float* __restrict__ P) {
    extern __shared__ __nv_bfloat16 smem[];
    unsigned smem_u32 = (unsigned)__cvta_generic_to_shared(smem);

    int t = threadIdx.x;
    int bm = blockIdx.y * BM, bn = blockIdx.x * BN;
    int kz = blockIdx.z;
    const __nv_bfloat16* Ab = A  + (size_t)kz * F2K;
    const __nv_bfloat16* Bb = Bt + (size_t)kz * F2K;
    float* Pb = P + (size_t)kz * RB * CC;

    int w = t >> 5, lane = t & 31;
    int g = lane >> 2, t2 = (lane & 3) * 2;
    int wm = (w >> 2) * 64, wn = (w & 3) * 32;

    int l7 = lane & 7, mmat = lane >> 3;
    unsigned a_row_base = (unsigned)(wm + (mmat & 1) * 8 + l7);
    unsigned a_khalf    = (unsigned)((mmat >> 1) * 16);
    unsigned b_row_base = (unsigned)(wn + (mmat >> 1) * 8 + l7);
    unsigned b_khalf    = (unsigned)((mmat & 1) * 16);

    float acc[4][4][4];
#pragma unroll
    for (int mi = 0; mi < 4; mi++)
#pragma unroll
        for (int ni = 0; ni < 4; ni++)
#pragma unroll
            for (int c = 0; c < 4; c++) acc[mi][ni][c] = 0.f;

    const int nk = F2K / BK;   // 24

    auto load_tile = [&](int kt, int s) {
        unsigned abase = smem_u32 + (unsigned)(s * STAGE_BYTES);
        unsigned bbase = abase + (unsigned)(BM * BK * 2);
#pragma unroll
        for (int i = 0; i < 4; i++) {
            int idx = t + 256 * i;
            int row = idx >> 3, seg = idx & 7;
            unsigned off = sw128((unsigned)(row * 128 + seg * 16));
            const __nv_bfloat16* ap = Ab + (size_t)(bm + row) * F2LD + kt * BK + seg * 8;
            const __nv_bfloat16* bp = Bb + (size_t)(bn + row) * F2LD + kt * BK + seg * 8;
            cpa16_r(abase + off, ap);
            cpa16_r(bbase + off, bp);
        }
    };

    load_tile(0, 0); cp_commit();
    load_tile(1, 1); cp_commit();

    for (int kt = 0; kt < nk; kt++) {
        int s = kt % 3;
        if (kt + 1 < nk) cp_wait1(); else cp_wait0();
        __syncthreads();
        if (kt + 2 < nk) {
            load_tile(kt + 2, (kt + 2) % 3);
            cp_commit();
        }

        unsigned abase = smem_u32 + (unsigned)(s * STAGE_BYTES);
        unsigned bbase = abase + (unsigned)(BM * BK * 2);

#pragma unroll
        for (int ks = 0; ks < 4; ks++) {
            unsigned af[4][4], bfr[4][2];
#pragma unroll
            for (int mi = 0; mi < 4; mi++) {
                unsigned off = sw128((a_row_base + mi * 16) * 128 + (unsigned)(ks * 32) + a_khalf);
                ldsm_x4(af[mi][0], af[mi][1], af[mi][2], af[mi][3], abase + off);
            }
#pragma unroll
            for (int p = 0; p < 2; p++) {
                unsigned off = sw128((b_row_base + p * 16) * 128 + (unsigned)(ks * 32) + b_khalf);
                unsigned r0, r1, r2, r3;
                ldsm_x4(r0, r1, r2, r3, bbase + off);
                bfr[2 * p][0] = r0;     bfr[2 * p][1] = r1;
                bfr[2 * p + 1][0] = r2; bfr[2 * p + 1][1] = r3;
            }
#pragma unroll
            for (int mi = 0; mi < 4; mi++)
#pragma unroll
                for (int ni = 0; ni < 4; ni++)
                    mma_bf16(acc[mi][ni][0], acc[mi][ni][1], acc[mi][ni][2], acc[mi][ni][3],
                             af[mi][0], af[mi][1], af[mi][2], af[mi][3],
                             bfr[ni][0], bfr[ni][1]);
        }
        __syncthreads();
    }

#pragma unroll
    for (int mi = 0; mi < 4; mi++) {
#pragma unroll
        for (int half = 0; half < 2; half++) {
            int m = bm + wm + mi * 16 + g + half * 8;
#pragma unroll
            for (int ni = 0; ni < 4; ni++) {
                int col = bn + wn + ni * 8 + t2;
                *(float2*)(Pb + (size_t)m * CC + col) =
                    make_float2(acc[mi][ni][half * 2 + 0], acc[mi][ni][half * 2 + 1]);
            }
        }
    }
}

// ---------------- bf16 flash attention: QT=64, 4 warps, cp.async K/V ---------
// 64 q-rows/block, 64-key tiles, 4 warps x 16 q-rows, double-buffered K/V.
#define QT 64
#define KT 64
#define AST 72
#define ATTN_SMEM ((QT + 4 * KT) * AST * 2)    // 64+256 rows = 46080 B

__global__ __launch_bounds__(128)
void attn_mma_kernel(const __nv_bfloat16* __restrict__ qkvb,
                     const __nv_bfloat16* __restrict__ vt,
                     const unsigned char* __restrict__ mask,
                     __nv_bfloat16* __restrict__ o) {
    extern __shared__ __nv_bfloat16 ash[];
    unsigned Qu = (unsigned)__cvta_generic_to_shared(ash);
    unsigned Ku = Qu + QT * AST * 2;
    unsigned Vu = Ku + 2 * KT * AST * 2;

    int t = threadIdx.x;
    int w = t >> 5, lane = t & 31;
    int g = lane >> 2, t2 = (lane & 3) * 2;
    int qt = blockIdx.x, bh = blockIdx.y;
    int b = bh / HH, head = bh % HH;
    int qbase = qt * QT;
    size_t base = (size_t)b * NTOK;

    int l7 = lane & 7, mmat = lane >> 3;
    unsigned a_base = Qu +
        (unsigned)(((w * 16 + (mmat & 1) * 8 + l7) * AST + (mmat >> 1) * 8) * 2);
    unsigned kv_off = (unsigned)((((mmat >> 1) * 8 + l7) * AST + (mmat & 1) * 8) * 2);

    auto load_kv = [&](int kt2, int buf) {
        int kbase = kt2 * KT;
        unsigned kb = Ku + (unsigned)(buf * KT * AST * 2);
        unsigned vb = Vu + (unsigned)(buf * KT * AST * 2);
#pragma unroll
        for (int i = 0; i < 4; i++) {
            int id = t + 128 * i;                  // 512 chunks over 128 threads
            int row = id >> 3, seg = id & 7;
            cpa16_r(kb + (unsigned)(row * AST * 2 + seg * 16),
                    qkvb + (base + kbase + row) * (size_t)(3 * CC) + CC + head * DD + seg * 8);
            cpa16_r(vb + (unsigned)(row * AST * 2 + seg * 16),
                    vt + (size_t)(bh * DD + row) * NTOK + kbase + seg * 8);
        }
        cp_commit();
    };

    // Q (64 rows x 8 segs = 512 chunks) + tile 0 share commit group 0
#pragma unroll
    for (int i = 0; i < 4; i++) {
        int id = t + 128 * i;
        int row = id >> 3, seg = id & 7;
        cpa16_r(Qu + (unsigned)(row * AST * 2 + seg * 16),
                qkvb + (base + qbase + row) * (size_t)(3 * CC) + head * DD + seg * 8);
    }
    load_kv(0, 0);

    int r0 = w * 16 + g;
    const unsigned char* mrow0 = mask + (size_t)(qbase + r0) * NTOK;
    const unsigned char* mrow1 = mrow0 + (size_t)8 * NTOK;

    float m0 = -1e30f, m1 = -1e30f, l0 = 0.f, l1 = 0.f;
    float oacc[8][4];
#pragma unroll
    for (int nd = 0; nd < 8; nd++)
#pragma unroll
        for (int c = 0; c < 4; c++) oacc[nd][c] = 0.f;

    for (int kt2 = 0; kt2 < NTOK / KT; kt2++) {
        int buf = kt2 & 1;
        int kbase = kt2 * KT;
        cp_wait0();
        __syncthreads();
        if (kt2 + 1 < NTOK / KT) load_kv(kt2 + 1, buf ^ 1);

        unsigned Kbuf = Ku + (unsigned)(buf * KT * AST * 2);
        unsigned Vbuf = Vu + (unsigned)(buf * KT * AST * 2);

        // S = Q @ K^T
        float sacc[8][4];
#pragma unroll
        for (int nb = 0; nb < 8; nb++)
#pragma unroll
            for (int c = 0; c < 4; c++) sacc[nb][c] = 0.f;
#pragma unroll
        for (int ds = 0; ds < 4; ds++) {
            unsigned a0, a1, a2, a3;
            ldsm_x4(a0, a1, a2, a3, a_base + (unsigned)(ds * 32));
#pragma unroll
            for (int p = 0; p < 4; p++) {
                unsigned r0v, r1v, r2v, r3v;
                ldsm_x4(r0v, r1v, r2v, r3v,
                        Kbuf + (unsigned)(p * 16 * AST * 2) + kv_off + (unsigned)(ds * 32));
                mma_bf16(sacc[2 * p][0], sacc[2 * p][1], sacc[2 * p][2], sacc[2 * p][3],
                         a0, a1, a2, a3, r0v, r1v);
                mma_bf16(sacc[2 * p + 1][0], sacc[2 * p + 1][1],
                         sacc[2 * p + 1][2], sacc[2 * p + 1][3],
                         a0, a1, a2, a3, r2v, r3v);
            }
        }

        // scale + mask + row max
        float rmax0 = -1e30f, rmax1 = -1e30f;
#pragma unroll
        for (int nb = 0; nb < 8; nb++) {
            uchar2 mq0 = *(const uchar2*)(mrow0 + kbase + nb * 8 + t2);
            uchar2 mq1 = *(const uchar2*)(mrow1 + kbase + nb * 8 + t2);
            float s00 = mq0.x ? -1e30f : sacc[nb][0] * 0.125f;
            float s01 = mq0.y ? -1e30f : sacc[nb][1] * 0.125f;
            float s10 = mq1.x ? -1e30f : sacc[nb][2] * 0.125f;
            float s11 = mq1.y ? -1e30f : sacc[nb][3] * 0.125f;
            sacc[nb][0] = s00; sacc[nb][1] = s01; sacc[nb][2] = s10; sacc[nb][3] = s11;
            rmax0 = fmaxf(rmax0, fmaxf(s00, s01));
            rmax1 = fmaxf(rmax1, fmaxf(s10, s11));
        }
#pragma unroll
        for (int off = 1; off < 4; off <<= 1) {
            rmax0 = fmaxf(rmax0, __shfl_xor_sync(0xffffffffu, rmax0, off));
            rmax1 = fmaxf(rmax1, __shfl_xor_sync(0xffffffffu, rmax1, off));
        }
        float mn0 = fmaxf(m0, rmax0), mn1 = fmaxf(m1, rmax1);
        float al0 = __expf(m0 - mn0), al1 = __expf(m1 - mn1);
        m0 = mn0; m1 = mn1;

        // exp -> P fragments + row sums
        unsigned pr0[8], pr1[8];
        float rs0 = 0.f, rs1 = 0.f;
#pragma unroll
        for (int nb = 0; nb < 8; nb++) {
            float p00 = __expf(sacc[nb][0] - mn0);
            float p01 = __expf(sacc[nb][1] - mn0);
            float p10 = __expf(sacc[nb][2] - mn1);
            float p11 = __expf(sacc[nb][3] - mn1);
            rs0 += p00 + p01; rs1 += p10 + p11;
            pr0[nb] = bf2_as_u32(__floats2bfloat162_rn(p00, p01));
            pr1[nb] = bf2_as_u32(__floats2bfloat162_rn(p10, p11));
        }
#pragma unroll
        for (int off = 1; off < 4; off <<= 1) {
            rs0 += __shfl_xor_sync(0xffffffffu, rs0, off);
            rs1 += __shfl_xor_sync(0xffffffffu, rs1, off);
        }
        l0 = l0 * al0 + rs0;
        l1 = l1 * al1 + rs1;

        // O = O*alpha + P @ V
#pragma unroll
        for (int nd = 0; nd < 8; nd++) {
            oacc[nd][0] *= al0; oacc[nd][1] *= al0;
            oacc[nd][2] *= al1; oacc[nd][3] *= al1;
        }
#pragma unroll
        for (int kb = 0; kb < 4; kb++) {
            unsigned a0 = pr0[2 * kb],     a1 = pr1[2 * kb];
            unsigned a2 = pr0[2 * kb + 1], a3 = pr1[2 * kb + 1];
#pragma unroll
            for (int p = 0; p < 4; p++) {
                unsigned r0v, r1v, r2v, r3v;
                ldsm_x4(r0v, r1v, r2v, r3v,
                        Vbuf + (unsigned)(p * 16 * AST * 2) + kv_off + (unsigned)(kb * 32));
                mma_bf16(oacc[2 * p][0], oacc[2 * p][1], oacc[2 * p][2], oacc[2 * p][3],
                         a0, a1, a2, a3, r0v, r1v);
                mma_bf16(oacc[2 * p + 1][0], oacc[2 * p + 1][1],
                         oacc[2 * p + 1][2], oacc[2 * p + 1][3],
                         a0, a1, a2, a3, r2v, r3v);
            }
        }
    }

    float inv0 = 1.0f / l0, inv1 = 1.0f / l1;
    __nv_bfloat16* op0 = o + (base + qbase + r0) * (size_t)CC + head * DD;
    __nv_bfloat16* op1 = op0 + (size_t)8 * CC;
#pragma unroll
    for (int nd = 0; nd < 8; nd++) {
        *(__nv_bfloat162*)(op0 + nd * 8 + t2) =
            __floats2bfloat162_rn(oacc[nd][0] * inv0, oacc[nd][1] * inv0);
        *(__nv_bfloat162*)(op1 + nd * 8 + t2) =
            __floats2bfloat162_rn(oacc[nd][2] * inv1, oacc[nd][3] * inv1);
    }
}

// ---------------- launch ----------------
extern "C" void kernel_launch(void* const* d_in, const int* in_sizes, int n_in,
                              void* d_out, int out_size) {
    (void)in_sizes; (void)n_in; (void)out_size;
    const float* x            = (const float*)d_in[0];
    const unsigned char* mask = (const unsigned char*)d_in[1];
    const float* ln1_g  = (const float*)d_in[2];
    const float* ln1_b  = (const float*)d_in[3];
    const float* w_qkv  = (const float*)d_in[4];
    const float* b_qkv  = (const float*)d_in[5];
    const float* w_proj = (const float*)d_in[6];
    const float* b_proj = (const float*)d_in[7];
    const float* ls1    = (const float*)d_in[8];
    const float* ln2_g  = (const float*)d_in[9];
    const float* ln2_b  = (const float*)d_in[10];
    const float* w1     = (const float*)d_in[11];
    const float* b1     = (const float*)d_in[12];
    const float* w2     = (const float*)d_in[13];
    const float* b2     = (const float*)d_in[14];
    const float* ls2    = (const float*)d_in[15];
    float* out = (float*)d_out;

    __nv_bfloat16 *h1b, *qkvb, *vt, *oatb, *ffnb, *wqkvT, *wprojT, *w1T, *w2T;
    float *x1, *fc2p;
    cudaGetSymbolAddress((void**)&h1b,   d_h1b);
    cudaGetSymbolAddress((void**)&qkvb,  d_qkvb);
    cudaGetSymbolAddress((void**)&vt,    d_vt);
    cudaGetSymbolAddress((void**)&oatb,  d_oatb);
    cudaGetSymbolAddress((void**)&x1,    d_x1);
    cudaGetSymbolAddress((void**)&ffnb,  d_ffnb);
    cudaGetSymbolAddress((void**)&fc2p,  d_fc2p);
    cudaGetSymbolAddress((void**)&wqkvT, d_wqkvT);
    cudaGetSymbolAddress((void**)&wprojT,d_wprojT);
    cudaGetSymbolAddress((void**)&w1T,   d_w1T);
    cudaGetSymbolAddress((void**)&w2T,   d_w2T);

    cudaFuncSetAttribute(gemm_bf16<0, __nv_bfloat16>,
                         cudaFuncAttributeMaxDynamicSharedMemorySize, GEMM_SMEM);
    cudaFuncSetAttribute(gemm_bf16<1, __nv_bfloat16>,
                         cudaFuncAttributeMaxDynamicSharedMemorySize, GEMM_SMEM);
    cudaFuncSetAttribute(gemm_bf16<2, float>,
                         cudaFuncAttributeMaxDynamicSharedMemorySize, GEMM_SMEM);
    cudaFuncSetAttribute(gemm_fc2k,
                         cudaFuncAttributeMaxDynamicSharedMemorySize, GEMM_SMEM);
    cudaFuncSetAttribute(attn_mma_kernel,
                         cudaFuncAttributeMaxDynamicSharedMemorySize, ATTN_SMEM);

    dim3 tb(32, 8);
    convT4_kernel<<<6912, tb>>>(w_qkv, wqkvT, w_proj, wprojT, w1, w1T, w2, w2T);   // 0
    ln_kernel<<<RB, 256>>>(x, ln1_g, ln1_b, h1b);                                   // 1
    gemm_bf16<0, __nv_bfloat16><<<dim3(3 * CC / BN, RB / BM), 256, GEMM_SMEM>>>(    // 2
        h1b, wqkvT, b_qkv, qkvb, RB, 3 * CC, CC, nullptr, nullptr);
    vtrans_kernel<<<dim3(NTOK / 32, DD / 32, 2 * HH), tb>>>(qkvb, vt);              // 3
    attn_mma_kernel<<<dim3(NTOK / QT, 2 * HH), 128, ATTN_SMEM>>>(qkvb, vt, mask, oatb); // 4
    gemm_bf16<2, float><<<dim3(CC / BN, RB / BM), 256, GEMM_SMEM>>>(                // 5
        oatb, wprojT, b_proj, x1, RB, CC, CC, x, ls1);
    ln_kernel<<<RB, 256>>>(x1, ln2_g, ln2_b, h1b);                                  // 6
    gemm_bf16<1, __nv_bfloat16><<<dim3(4 * CC / BN, RB / BM), 256, GEMM_SMEM>>>(    // 7
        h1b, w1T, b1, ffnb, RB, 4 * CC, CC, nullptr, nullptr);
    gemm_fc2k<<<dim3(CC / BN, RB / BM, 2), 256, GEMM_SMEM>>>(ffnb, w2T, fc2p);      // 8
    combine_fc2<<<RB * CC / 4 / 256, 256>>>(fc2p, x1, b2, ls2, out);                // 9
}